// round 5
// baseline (speedup 1.0000x reference)
#include <cuda_runtime.h>
#include <math.h>

#define NSAMP 4096
#define NFFT 256
#define HOP 64
#define NFRAMES 65
#define NBINS 129
#define NB 64          // batch
#define NE 8           // experts
#define CH 64          // channels
#define L1LEN 2048
#define L2LEN 1024
#define TOUT 128       // output t per tile
#define NTILES (L2LEN / TOUT)
#define H1STRIDE 260   // conv1 tile row: j = 0..256 (+3 pad)

// scratch (no allocations allowed)
__device__ float g_mag[NB * NFRAMES * NBINS];   // per-frame magnitudes
__device__ int   g_eidx[NB * 2];
__device__ float g_ew[NB * 2];

// ---------------------------------------------------------------------------
// packed fp32x2 helpers (FFMA2: full-rate 128 FMA/cyc/SM vs 64 for 3-reg FFMA)
// ---------------------------------------------------------------------------
__device__ __forceinline__ unsigned long long packf2(float lo, float hi) {
    unsigned long long d;
    asm("mov.b64 %0, {%1, %2};"
        : "=l"(d) : "r"(__float_as_uint(lo)), "r"(__float_as_uint(hi)));
    return d;
}
__device__ __forceinline__ void fmaf2(unsigned long long& d,
                                      unsigned long long a,
                                      unsigned long long b) {
    asm("fma.rn.f32x2 %0, %1, %2, %0;" : "+l"(d) : "l"(a), "l"(b));
}
__device__ __forceinline__ void unpackf2(float& lo, float& hi,
                                         unsigned long long v) {
    unsigned int a, b;
    asm("mov.b64 {%0, %1}, %2;" : "=r"(a), "=r"(b) : "l"(v));
    lo = __uint_as_float(a);
    hi = __uint_as_float(b);
}

// ---------------------------------------------------------------------------
// Kernel 1: STFT magnitudes. grid (NFRAMES, NB), 256 threads.
// Phasor rotation recurrence, 4 interleaved chains -> no table LDS at all.
// ---------------------------------------------------------------------------
__global__ void __launch_bounds__(256) k_stft(const float* __restrict__ x) {
    __shared__ float f[NFFT];
    const int fr = blockIdx.x;
    const int b  = blockIdx.y;
    const int t  = threadIdx.x;

    // reflect-padded sample: xp[j] with j = fr*HOP + t, pad=128
    int m = fr * HOP + t - 128;
    if (m < 0) m = -m;
    else if (m >= NSAMP) m = 2 * NSAMP - 2 - m;
    const float win = 0.5f - 0.5f * cospif((float)t / 128.0f);
    f[t] = x[b * NSAMP + m] * win;
    __syncthreads();

    if (t < NBINS) {
        const float ang = (float)t / 128.0f;       // theta / pi
        float c[4], s[4];
#pragma unroll
        for (int i = 0; i < 4; i++) {
            c[i] = cospif(ang * (float)i);
            s[i] = sinpif(ang * (float)i);
        }
        const float cD = cospif(ang * 4.0f);
        const float sD = sinpif(ang * 4.0f);
        float re_[4] = {0.f, 0.f, 0.f, 0.f};
        float im_[4] = {0.f, 0.f, 0.f, 0.f};
#pragma unroll 4
        for (int n4 = 0; n4 < 64; n4++) {
#pragma unroll
            for (int i = 0; i < 4; i++) {
                const float v = f[n4 * 4 + i];
                re_[i] += v * c[i];
                im_[i] += v * s[i];
                const float cn = c[i] * cD - s[i] * sD;
                s[i] = c[i] * sD + s[i] * cD;
                c[i] = cn;
            }
        }
        const float re = (re_[0] + re_[1]) + (re_[2] + re_[3]);
        const float im = (im_[0] + im_[1]) + (im_[2] + im_[3]);
        g_mag[(b * NFRAMES + fr) * NBINS + t] = sqrtf(re * re + im * im);
    }
}

// ---------------------------------------------------------------------------
// Kernel 2: pooling + gating MLP + top-2 + softmax. grid (NB), 256 threads.
// ---------------------------------------------------------------------------
__global__ void __launch_bounds__(256) k_gate(
    const float* __restrict__ Wg1, const float* __restrict__ bg1,
    const float* __restrict__ Wg2, const float* __restrict__ bg2,
    const float* __restrict__ Wg3, const float* __restrict__ bg3) {
    __shared__ float p[NBINS];
    __shared__ float h1[256];
    __shared__ float h2[128];
    __shared__ float lg[NE];
    const int b = blockIdx.x;
    const int t = threadIdx.x;

    if (t < NBINS) {
        float s = 0.f;
        for (int fr = 0; fr < NFRAMES; fr++)
            s += g_mag[(b * NFRAMES + fr) * NBINS + t];
        p[t] = s * (1.0f / NFRAMES);
    }
    __syncthreads();

    {   // 129 -> 256
        float s = bg1[t];
        for (int i = 0; i < NBINS; i++) s += p[i] * Wg1[i * 256 + t];
        h1[t] = fmaxf(s, 0.f);
    }
    __syncthreads();
    if (t < 128) {  // 256 -> 128
        float s = bg2[t];
        for (int i = 0; i < 256; i++) s += h1[i] * Wg2[i * 128 + t];
        h2[t] = fmaxf(s, 0.f);
    }
    __syncthreads();
    if (t < NE) {   // 128 -> 8
        float s = bg3[t];
        for (int i = 0; i < 128; i++) s += h2[i] * Wg3[i * NE + t];
        lg[t] = s;
    }
    __syncthreads();
    if (t == 0) {
        int i0 = 0; float v0 = lg[0];
        for (int j = 1; j < NE; j++) if (lg[j] > v0) { v0 = lg[j]; i0 = j; }
        int i1 = (i0 == 0) ? 1 : 0; float v1 = lg[i1];
        for (int j = 0; j < NE; j++)
            if (j != i0 && lg[j] > v1) { v1 = lg[j]; i1 = j; }
        const float e = expf(v1 - v0);
        const float inv = 1.f / (1.f + e);
        g_eidx[b * 2] = i0; g_eidx[b * 2 + 1] = i1;
        g_ew[b * 2] = inv;  g_ew[b * 2 + 1] = e * inv;
    }
}

// ---------------------------------------------------------------------------
// Kernel 3: fused top-2 expert conv stack.
// grid (NTILES, 3 branches, NB), 256 threads, ~120KB dyn smem (1 block/SM).
// conv1 (stride2, pad ksz/2) -> relu -> smem h1 tile (64 x 257); conv2 (k3,
// stride2, pad1) with 4c x 8t register tiles using packed f32x2 FMA; fused
// weighted sum of the two experts.
// wbs smem layout: [r=ci*3+k][c ^ ((r&7)<<2)] -> conflict-free float4 reads.
// ---------------------------------------------------------------------------
#define XS_LEN 528
#define SMEM_FLOATS (XS_LEN + 448 + 64 + 64 + 192 * 64 + CH * H1STRIDE)

__global__ void __launch_bounds__(256) k_expert(
    float* __restrict__ out, const float* __restrict__ x,
    const float* __restrict__ wa3, const float* __restrict__ ba3,
    const float* __restrict__ wb3, const float* __restrict__ bb3,
    const float* __restrict__ wa5, const float* __restrict__ ba5,
    const float* __restrict__ wb5, const float* __restrict__ bb5,
    const float* __restrict__ wa7, const float* __restrict__ ba7,
    const float* __restrict__ wb7, const float* __restrict__ bb7) {
    extern __shared__ float smem[];
    float* xs  = smem;            // 528
    float* was = xs + XS_LEN;     // up to 64*7
    float* bas = was + 448;       // 64
    float* bbs = bas + 64;        // 64
    float* wbs = bbs + 64;        // 192*64
    float* h1s = wbs + 192 * 64;  // 64*260

    const int tid  = threadIdx.x;
    const int tile = blockIdx.x;
    const int br   = blockIdx.y;
    const int b    = blockIdx.z;
    const int t0   = tile * TOUT;
    const int ksz  = 3 + 2 * br;
    const int pad  = ksz >> 1;

    const float* wap = (br == 0) ? wa3 : ((br == 1) ? wa5 : wa7);
    const float* bap = (br == 0) ? ba3 : ((br == 1) ? ba5 : ba7);
    const float* wbp = (br == 0) ? wb3 : ((br == 1) ? wb5 : wb7);
    const float* bbp = (br == 0) ? bb3 : ((br == 1) ? bb5 : bb7);

    const int   eidx[2] = { g_eidx[b * 2], g_eidx[b * 2 + 1] };
    const float ewgt[2] = { g_ew[b * 2],   g_ew[b * 2 + 1] };

    // x window for this tile: xi in [4*t0-5, 4*t0+522]; zero-fill pad
    const int xlo = 4 * t0 - 5;
    for (int i = tid; i < XS_LEN; i += 256) {
        const int xi = xlo + i;
        xs[i] = (xi >= 0 && xi < NSAMP) ? x[b * NSAMP + xi] : 0.f;
    }

    const int cg = tid & 15;          // channel group 0..15 (4 ch each)
    const int tg = tid >> 4;          // t group 0..15 (8 t each)
    const int cbase = cg * 4;

    float facc[32];                   // [c 0..3][t-offset 0..7]
#pragma unroll
    for (int i = 0; i < 32; i++) facc[i] = 0.f;

    for (int ei = 0; ei < 2; ei++) {
        const int   e   = eidx[ei];
        const float wgt = ewgt[ei];
        __syncthreads();   // xs ready (ei=0) / prev conv2 done reading (ei=1)

        // stage expert weights
        const float* wa = wap + e * CH * ksz;
        for (int i = tid; i < CH * ksz; i += 256) was[i] = wa[i];
        if (tid < CH) {
            bas[tid] = bap[e * CH + tid];
            bbs[tid] = bbp[e * CH + tid];
        }
        const float* wb = wbp + e * CH * CH * 3;
        for (int i = tid; i < CH * 192; i += 256) {   // coalesced gmem read
            const int c = i / 192;
            const int r = i - c * 192;                // ci*3 + k
            wbs[r * 64 + (c ^ ((r & 7) << 2))] = wb[i];
        }
        __syncthreads();

        // conv1 -> h1s[c][j], j=0..256 maps to p = 2*t0 - 1 + j
        for (int idx = tid; idx < CH * H1STRIDE; idx += 256) {
            const int c = idx / H1STRIDE;
            const int j = idx - c * H1STRIDE;
            const int p = 2 * t0 - 1 + j;
            float s = bas[c];
            const float* wr = &was[c * ksz];
            const int off = 2 * j + (3 - pad);
            for (int k = 0; k < ksz; k++) s += wr[k] * xs[off + k];
            h1s[idx] = (p >= 0 && p < L1LEN) ? fmaxf(s, 0.f) : 0.f;
        }
        __syncthreads();

        // conv2: 4 channels x 8 t per thread, packed pairs over t
        unsigned long long acc[16];   // [c 0..3][t-pair 0..3]
#pragma unroll
        for (int i = 0; i < 16; i++) acc[i] = 0ull;

#pragma unroll 2
        for (int ci = 0; ci < CH; ci++) {
            const float* hb = &h1s[ci * H1STRIDE + tg * 16];
            float hv[20];
            *(float4*)(hv)      = *(const float4*)(hb);
            *(float4*)(hv + 4)  = *(const float4*)(hb + 4);
            *(float4*)(hv + 8)  = *(const float4*)(hb + 8);
            *(float4*)(hv + 12) = *(const float4*)(hb + 12);
            *(float4*)(hv + 16) = *(const float4*)(hb + 16);

            unsigned long long hp[15];   // hp[4p+k] = (h[4p+k], h[4p+k+2])
#pragma unroll
            for (int p = 0; p < 4; p++)
#pragma unroll
                for (int k = 0; k < 3; k++) {
                    const int q = 4 * p + k;
                    hp[q] = packf2(hv[q], hv[q + 2]);
                }

            const int r0 = ci * 3;
            const float4 w0 = *(const float4*)&wbs[ r0      * 64 + (cbase ^ (( r0      & 7) << 2))];
            const float4 w1 = *(const float4*)&wbs[(r0 + 1) * 64 + (cbase ^ (((r0 + 1) & 7) << 2))];
            const float4 w2 = *(const float4*)&wbs[(r0 + 2) * 64 + (cbase ^ (((r0 + 2) & 7) << 2))];
            unsigned long long wp0[4], wp1[4], wp2[4];
            wp0[0] = packf2(w0.x, w0.x); wp0[1] = packf2(w0.y, w0.y);
            wp0[2] = packf2(w0.z, w0.z); wp0[3] = packf2(w0.w, w0.w);
            wp1[0] = packf2(w1.x, w1.x); wp1[1] = packf2(w1.y, w1.y);
            wp1[2] = packf2(w1.z, w1.z); wp1[3] = packf2(w1.w, w1.w);
            wp2[0] = packf2(w2.x, w2.x); wp2[1] = packf2(w2.y, w2.y);
            wp2[2] = packf2(w2.z, w2.z); wp2[3] = packf2(w2.w, w2.w);

#pragma unroll
            for (int c = 0; c < 4; c++)
#pragma unroll
                for (int p = 0; p < 4; p++) {
                    fmaf2(acc[c * 4 + p], hp[4 * p + 0], wp0[c]);
                    fmaf2(acc[c * 4 + p], hp[4 * p + 1], wp1[c]);
                    fmaf2(acc[c * 4 + p], hp[4 * p + 2], wp2[c]);
                }
        }

        // epilogue: bias + relu + gate-weighted accumulate
#pragma unroll
        for (int c = 0; c < 4; c++) {
            const float bias = bbs[cbase + c];
#pragma unroll
            for (int p = 0; p < 4; p++) {
                float lo, hi;
                unpackf2(lo, hi, acc[c * 4 + p]);
                facc[c * 8 + 2 * p]     += wgt * fmaxf(lo + bias, 0.f);
                facc[c * 8 + 2 * p + 1] += wgt * fmaxf(hi + bias, 0.f);
            }
        }
    }

    const int t_out = t0 + tg * 8;
#pragma unroll
    for (int c = 0; c < 4; c++) {
        const int row = b * 192 + br * 64 + cbase + c;
        *(float4*)&out[(size_t)row * L2LEN + t_out] =
            make_float4(facc[c * 8 + 0], facc[c * 8 + 1],
                        facc[c * 8 + 2], facc[c * 8 + 3]);
        *(float4*)&out[(size_t)row * L2LEN + t_out + 4] =
            make_float4(facc[c * 8 + 4], facc[c * 8 + 5],
                        facc[c * 8 + 6], facc[c * 8 + 7]);
    }
}

// ---------------------------------------------------------------------------
extern "C" void kernel_launch(void* const* d_in, const int* in_sizes, int n_in,
                              void* d_out, int out_size) {
    const float* x   = (const float*)d_in[0];
    const float* Wg1 = (const float*)d_in[1];
    const float* bg1 = (const float*)d_in[2];
    const float* Wg2 = (const float*)d_in[3];
    const float* bg2 = (const float*)d_in[4];
    const float* Wg3 = (const float*)d_in[5];
    const float* bg3 = (const float*)d_in[6];
    const float* wa3 = (const float*)d_in[7];
    const float* ba3 = (const float*)d_in[8];
    const float* wb3 = (const float*)d_in[9];
    const float* bb3 = (const float*)d_in[10];
    const float* wa5 = (const float*)d_in[11];
    const float* ba5 = (const float*)d_in[12];
    const float* wb5 = (const float*)d_in[13];
    const float* bb5 = (const float*)d_in[14];
    const float* wa7 = (const float*)d_in[15];
    const float* ba7 = (const float*)d_in[16];
    const float* wb7 = (const float*)d_in[17];
    const float* bb7 = (const float*)d_in[18];
    float* out = (float*)d_out;

    k_stft<<<dim3(NFRAMES, NB), 256>>>(x);
    k_gate<<<NB, 256>>>(Wg1, bg1, Wg2, bg2, Wg3, bg3);

    const int smem_bytes = SMEM_FLOATS * sizeof(float);
    (void)cudaFuncSetAttribute(k_expert,
                               cudaFuncAttributeMaxDynamicSharedMemorySize,
                               smem_bytes);
    k_expert<<<dim3(NTILES, 3, NB), 256, smem_bytes>>>(
        out, x,
        wa3, ba3, wb3, bb3,
        wa5, ba5, wb5, bb5,
        wa7, ba7, wb7, bb7);
}

// round 6
// speedup vs baseline: 1.1287x; 1.1287x over previous
#include <cuda_runtime.h>
#include <math.h>

#define NSAMP 4096
#define NFFT 256
#define HOP 64
#define NFRAMES 65
#define NBINS 129
#define NB 64          // batch
#define NE 8           // experts
#define CH 64          // channels
#define L1LEN 2048
#define L2LEN 1024
#define TOUT 128       // output t per tile
#define NTILES (L2LEN / TOUT)
#define PL 128         // plane stride (floats)

// scratch (no allocations allowed)
__device__ float g_mag[NB * NFRAMES * NBINS];   // per-frame magnitudes
__device__ int   g_eidx[NB * 2];
__device__ float g_ew[NB * 2];

// ---------------------------------------------------------------------------
// packed fp32x2 helpers
// ---------------------------------------------------------------------------
__device__ __forceinline__ unsigned long long packf2(float lo, float hi) {
    unsigned long long d;
    asm("mov.b64 %0, {%1, %2};"
        : "=l"(d) : "r"(__float_as_uint(lo)), "r"(__float_as_uint(hi)));
    return d;
}
__device__ __forceinline__ void fmaf2(unsigned long long& d,
                                      unsigned long long a,
                                      unsigned long long b) {
    asm("fma.rn.f32x2 %0, %1, %2, %0;" : "+l"(d) : "l"(a), "l"(b));
}
__device__ __forceinline__ void unpackf2(float& lo, float& hi,
                                         unsigned long long v) {
    unsigned int a, b;
    asm("mov.b64 {%0, %1}, %2;" : "=r"(a), "=r"(b) : "l"(v));
    lo = __uint_as_float(a);
    hi = __uint_as_float(b);
}

// ---------------------------------------------------------------------------
// Kernel 1: STFT magnitudes. grid (NFRAMES, NB), 128 threads.
// Threads 1..127: phasor-rotation DFT (no table LDS). Thread 0: bins 0 & 128
// (plain / alternating sums).
// ---------------------------------------------------------------------------
__global__ void __launch_bounds__(128) k_stft(const float* __restrict__ x) {
    __shared__ float f[NFFT];
    const int fr = blockIdx.x;
    const int b  = blockIdx.y;
    const int t  = threadIdx.x;

    for (int i = t; i < NFFT; i += 128) {
        int m = fr * HOP + i - 128;           // reflect pad
        if (m < 0) m = -m;
        else if (m >= NSAMP) m = 2 * NSAMP - 2 - m;
        const float win = 0.5f - 0.5f * cospif((float)i / 128.0f);
        f[i] = x[b * NSAMP + m] * win;
    }
    __syncthreads();

    float* magp = &g_mag[(b * NFRAMES + fr) * NBINS];
    if (t == 0) {
        float s0 = 0.f, s1 = 0.f;
#pragma unroll 8
        for (int n = 0; n < NFFT; n += 2) { s0 += f[n]; s1 += f[n + 1]; }
        magp[0]   = fabsf(s0 + s1);
        magp[128] = fabsf(s0 - s1);
    } else {
        const float ang = (float)t / 128.0f;       // theta / pi
        float c[4], s[4];
#pragma unroll
        for (int i = 0; i < 4; i++) {
            c[i] = cospif(ang * (float)i);
            s[i] = sinpif(ang * (float)i);
        }
        const float cD = cospif(ang * 4.0f);
        const float sD = sinpif(ang * 4.0f);
        float re_[4] = {0.f, 0.f, 0.f, 0.f};
        float im_[4] = {0.f, 0.f, 0.f, 0.f};
#pragma unroll 4
        for (int n4 = 0; n4 < 64; n4++) {
#pragma unroll
            for (int i = 0; i < 4; i++) {
                const float v = f[n4 * 4 + i];
                re_[i] += v * c[i];
                im_[i] += v * s[i];
                const float cn = c[i] * cD - s[i] * sD;
                s[i] = c[i] * sD + s[i] * cD;
                c[i] = cn;
            }
        }
        const float re = (re_[0] + re_[1]) + (re_[2] + re_[3]);
        const float im = (im_[0] + im_[1]) + (im_[2] + im_[3]);
        magp[t] = sqrtf(re * re + im * im);
    }
}

// ---------------------------------------------------------------------------
// Kernel 2: pooling + gating MLP + top-2 + softmax. grid (NB), 256 threads.
// ---------------------------------------------------------------------------
__global__ void __launch_bounds__(256) k_gate(
    const float* __restrict__ Wg1, const float* __restrict__ bg1,
    const float* __restrict__ Wg2, const float* __restrict__ bg2,
    const float* __restrict__ Wg3, const float* __restrict__ bg3) {
    __shared__ float p[NBINS];
    __shared__ float h1[256];
    __shared__ float h2[128];
    __shared__ float lg[NE];
    const int b = blockIdx.x;
    const int t = threadIdx.x;

    if (t < NBINS) {
        float s = 0.f;
        for (int fr = 0; fr < NFRAMES; fr++)
            s += g_mag[(b * NFRAMES + fr) * NBINS + t];
        p[t] = s * (1.0f / NFRAMES);
    }
    __syncthreads();

    {   // 129 -> 256
        float s = bg1[t];
        for (int i = 0; i < NBINS; i++) s += p[i] * Wg1[i * 256 + t];
        h1[t] = fmaxf(s, 0.f);
    }
    __syncthreads();
    if (t < 128) {  // 256 -> 128
        float s = bg2[t];
        for (int i = 0; i < 256; i++) s += h1[i] * Wg2[i * 128 + t];
        h2[t] = fmaxf(s, 0.f);
    }
    __syncthreads();
    if (t < NE) {   // 128 -> 8
        float s = bg3[t];
        for (int i = 0; i < 128; i++) s += h2[i] * Wg3[i * NE + t];
        lg[t] = s;
    }
    __syncthreads();
    if (t == 0) {
        int i0 = 0; float v0 = lg[0];
        for (int j = 1; j < NE; j++) if (lg[j] > v0) { v0 = lg[j]; i0 = j; }
        int i1 = (i0 == 0) ? 1 : 0; float v1 = lg[i1];
        for (int j = 0; j < NE; j++)
            if (j != i0 && lg[j] > v1) { v1 = lg[j]; i1 = j; }
        const float e = expf(v1 - v0);
        const float inv = 1.f / (1.f + e);
        g_eidx[b * 2] = i0; g_eidx[b * 2 + 1] = i1;
        g_ew[b * 2] = inv;  g_ew[b * 2 + 1] = e * inv;
    }
}

// ---------------------------------------------------------------------------
// Kernel 3: fused top-2 expert conv stack.
// grid (NTILES, 3 branches, NB), 256 threads, ~148KB dyn smem (1 block/SM).
// conv1 writes three deinterleaved planes:
//   E[c][v] = h[2(t0+v)]      (even)
//   O[c][v] = h[2(t0+v) - 1]  (odd, left)
//   S[c][v] = h[2(t0+v) + 1]  (odd, right = O shifted; written in same pass)
// conv2: y[t] = w0*O[v] + w1*E[v] + w2*S[v]; t-pairs (v,v+1) map to aligned
// adjacent plane pairs -> FFMA2 with zero h-packing. Only 12 (w,w) broadcast
// packs per ci. wbs swizzle as before for conflict-free float4 w reads.
// ---------------------------------------------------------------------------
#define XS_LEN 528
#define SMEM_FLOATS (XS_LEN + 448 + 64 + 64 + 192 * 64 + 3 * CH * PL)

__global__ void __launch_bounds__(256) k_expert(
    float* __restrict__ out, const float* __restrict__ x,
    const float* __restrict__ wa3, const float* __restrict__ ba3,
    const float* __restrict__ wb3, const float* __restrict__ bb3,
    const float* __restrict__ wa5, const float* __restrict__ ba5,
    const float* __restrict__ wb5, const float* __restrict__ bb5,
    const float* __restrict__ wa7, const float* __restrict__ ba7,
    const float* __restrict__ wb7, const float* __restrict__ bb7) {
    extern __shared__ float smem[];
    float* xs  = smem;            // 528
    float* was = xs + XS_LEN;     // 448
    float* bas = was + 448;       // 64
    float* bbs = bas + 64;        // 64
    float* wbs = bbs + 64;        // 192*64
    float* Ep  = wbs + 192 * 64;  // 64*128
    float* Op  = Ep + CH * PL;    // 64*128
    float* Sp  = Op + CH * PL;    // 64*128

    const int tid  = threadIdx.x;
    const int tile = blockIdx.x;
    const int br   = blockIdx.y;
    const int b    = blockIdx.z;
    const int t0   = tile * TOUT;
    const int ksz  = 3 + 2 * br;
    const int pad  = ksz >> 1;

    const float* wap = (br == 0) ? wa3 : ((br == 1) ? wa5 : wa7);
    const float* bap = (br == 0) ? ba3 : ((br == 1) ? ba5 : ba7);
    const float* wbp = (br == 0) ? wb3 : ((br == 1) ? wb5 : wb7);
    const float* bbp = (br == 0) ? bb3 : ((br == 1) ? bb5 : bb7);

    const int   eidx[2] = { g_eidx[b * 2], g_eidx[b * 2 + 1] };
    const float ewgt[2] = { g_ew[b * 2],   g_ew[b * 2 + 1] };

    // x window: xi in [4*t0-5, 4*t0+522]; zero-fill out of range
    const int xlo = 4 * t0 - 5;
    for (int i = tid; i < XS_LEN; i += 256) {
        const int xi = xlo + i;
        xs[i] = (xi >= 0 && xi < NSAMP) ? x[b * NSAMP + xi] : 0.f;
    }

    const int cg = tid & 15;          // channel group (4 ch each)
    const int tg = tid >> 4;          // t group (8 t each)
    const int cbase = cg * 4;
    const int v0 = tg * 8;

    float facc[32];                   // [c 0..3][t-offset 0..7]
#pragma unroll
    for (int i = 0; i < 32; i++) facc[i] = 0.f;

    for (int ei = 0; ei < 2; ei++) {
        const int   e   = eidx[ei];
        const float wgt = ewgt[ei];
        __syncthreads();   // xs ready (ei=0) / prev conv2 done reading (ei=1)

        // stage expert weights
        const float* wa = wap + e * CH * ksz;
        for (int i = tid; i < CH * ksz; i += 256) was[i] = wa[i];
        if (tid < CH) {
            bas[tid] = bap[e * CH + tid];
            bbs[tid] = bbp[e * CH + tid];
        }
        const float* wb = wbp + e * CH * CH * 3;
        for (int i = tid; i < CH * 192; i += 256) {   // coalesced gmem read
            const int c = i / 192;
            const int r = i - c * 192;                // ci*3 + k
            wbs[r * 64 + (c ^ ((r & 7) << 2))] = wb[i];
        }
        __syncthreads();

        // conv1 even plane: E[c][u] = h[2t0+2u], u 0..127 (p<=2046, no guard)
        for (int idx = tid; idx < CH * PL; idx += 256) {
            const int c = idx >> 7;
            const int u = idx & 127;
            float s = bas[c];
            const float* wr = &was[c * ksz];
            const int off = 4 * u + 5 - pad;
            for (int k = 0; k < ksz; k++) s += wr[k] * xs[off + k];
            Ep[idx] = fmaxf(s, 0.f);
        }
        // conv1 odd chain: value at p = 2t0+2u-1 -> O[u] and S[u-1]
        for (int idx = tid; idx < CH * PL; idx += 256) {
            const int c = idx >> 7;
            const int u = idx & 127;
            const int p = 2 * t0 + 2 * u - 1;
            float s = bas[c];
            const float* wr = &was[c * ksz];
            const int off = 4 * u + 3 - pad;
            for (int k = 0; k < ksz; k++) s += wr[k] * xs[off + k];
            const float v = (p >= 0) ? fmaxf(s, 0.f) : 0.f;
            Op[idx] = v;
            if (u >= 1) Sp[idx - 1] = v;
        }
        if (tid < CH) {   // odd chain tail u'=128 -> S[c][127]; p = 2t0+255
            const int c = tid;
            float s = bas[c];
            const float* wr = &was[c * ksz];
            const int off = 4 * 128 + 3 - pad;
            for (int k = 0; k < ksz; k++) s += wr[k] * xs[off + k];
            Sp[c * PL + 127] = fmaxf(s, 0.f);
        }
        __syncthreads();

        // conv2: 4 channels x 8 t per thread; t-pairs via plane-adjacent FFMA2
        unsigned long long acc[16];   // [c 0..3][t-pair 0..3]
#pragma unroll
        for (int i = 0; i < 16; i++) acc[i] = 0ull;

#pragma unroll 2
        for (int ci = 0; ci < CH; ci++) {
            const float4 e0 = *(const float4*)&Ep[ci * PL + v0];
            const float4 e1 = *(const float4*)&Ep[ci * PL + v0 + 4];
            const float4 o0 = *(const float4*)&Op[ci * PL + v0];
            const float4 o1 = *(const float4*)&Op[ci * PL + v0 + 4];
            const float4 q0 = *(const float4*)&Sp[ci * PL + v0];
            const float4 q1 = *(const float4*)&Sp[ci * PL + v0 + 4];

            const unsigned long long pe[4] = {
                packf2(e0.x, e0.y), packf2(e0.z, e0.w),
                packf2(e1.x, e1.y), packf2(e1.z, e1.w) };
            const unsigned long long po[4] = {
                packf2(o0.x, o0.y), packf2(o0.z, o0.w),
                packf2(o1.x, o1.y), packf2(o1.z, o1.w) };
            const unsigned long long ps[4] = {
                packf2(q0.x, q0.y), packf2(q0.z, q0.w),
                packf2(q1.x, q1.y), packf2(q1.z, q1.w) };

            const int r0 = ci * 3;
            const float4 w0 = *(const float4*)&wbs[ r0      * 64 + (cbase ^ (( r0      & 7) << 2))];
            const float4 w1 = *(const float4*)&wbs[(r0 + 1) * 64 + (cbase ^ (((r0 + 1) & 7) << 2))];
            const float4 w2 = *(const float4*)&wbs[(r0 + 2) * 64 + (cbase ^ (((r0 + 2) & 7) << 2))];
            const unsigned long long wp0[4] = {
                packf2(w0.x, w0.x), packf2(w0.y, w0.y),
                packf2(w0.z, w0.z), packf2(w0.w, w0.w) };
            const unsigned long long wp1[4] = {
                packf2(w1.x, w1.x), packf2(w1.y, w1.y),
                packf2(w1.z, w1.z), packf2(w1.w, w1.w) };
            const unsigned long long wp2[4] = {
                packf2(w2.x, w2.x), packf2(w2.y, w2.y),
                packf2(w2.z, w2.z), packf2(w2.w, w2.w) };

#pragma unroll
            for (int c = 0; c < 4; c++)
#pragma unroll
                for (int pr = 0; pr < 4; pr++) {
                    fmaf2(acc[c * 4 + pr], po[pr], wp0[c]);
                    fmaf2(acc[c * 4 + pr], pe[pr], wp1[c]);
                    fmaf2(acc[c * 4 + pr], ps[pr], wp2[c]);
                }
        }

        // epilogue: bias + relu + gate-weighted accumulate
#pragma unroll
        for (int c = 0; c < 4; c++) {
            const float bias = bbs[cbase + c];
#pragma unroll
            for (int pr = 0; pr < 4; pr++) {
                float lo, hi;
                unpackf2(lo, hi, acc[c * 4 + pr]);
                facc[c * 8 + 2 * pr]     += wgt * fmaxf(lo + bias, 0.f);
                facc[c * 8 + 2 * pr + 1] += wgt * fmaxf(hi + bias, 0.f);
            }
        }
    }

    const int t_out = t0 + v0;
#pragma unroll
    for (int c = 0; c < 4; c++) {
        const int row = b * 192 + br * 64 + cbase + c;
        *(float4*)&out[(size_t)row * L2LEN + t_out] =
            make_float4(facc[c * 8 + 0], facc[c * 8 + 1],
                        facc[c * 8 + 2], facc[c * 8 + 3]);
        *(float4*)&out[(size_t)row * L2LEN + t_out + 4] =
            make_float4(facc[c * 8 + 4], facc[c * 8 + 5],
                        facc[c * 8 + 6], facc[c * 8 + 7]);
    }
}

// ---------------------------------------------------------------------------
extern "C" void kernel_launch(void* const* d_in, const int* in_sizes, int n_in,
                              void* d_out, int out_size) {
    const float* x   = (const float*)d_in[0];
    const float* Wg1 = (const float*)d_in[1];
    const float* bg1 = (const float*)d_in[2];
    const float* Wg2 = (const float*)d_in[3];
    const float* bg2 = (const float*)d_in[4];
    const float* Wg3 = (const float*)d_in[5];
    const float* bg3 = (const float*)d_in[6];
    const float* wa3 = (const float*)d_in[7];
    const float* ba3 = (const float*)d_in[8];
    const float* wb3 = (const float*)d_in[9];
    const float* bb3 = (const float*)d_in[10];
    const float* wa5 = (const float*)d_in[11];
    const float* ba5 = (const float*)d_in[12];
    const float* wb5 = (const float*)d_in[13];
    const float* bb5 = (const float*)d_in[14];
    const float* wa7 = (const float*)d_in[15];
    const float* ba7 = (const float*)d_in[16];
    const float* wb7 = (const float*)d_in[17];
    const float* bb7 = (const float*)d_in[18];
    float* out = (float*)d_out;

    k_stft<<<dim3(NFRAMES, NB), 128>>>(x);
    k_gate<<<NB, 256>>>(Wg1, bg1, Wg2, bg2, Wg3, bg3);

    const int smem_bytes = SMEM_FLOATS * sizeof(float);
    (void)cudaFuncSetAttribute(k_expert,
                               cudaFuncAttributeMaxDynamicSharedMemorySize,
                               smem_bytes);
    k_expert<<<dim3(NTILES, 3, NB), 256, smem_bytes>>>(
        out, x,
        wa3, ba3, wb3, bb3,
        wa5, ba5, wb5, bb5,
        wa7, ba7, wb7, bb7);
}

// round 9
// speedup vs baseline: 1.2846x; 1.1382x over previous
#include <cuda_runtime.h>
#include <cuda_bf16.h>
#include <math.h>
#include <stdint.h>

#define NSAMP 4096
#define NFFT 256
#define HOP 64
#define NFRAMES 65
#define NBINS 129
#define NB 64
#define NE 8
#define CH 64
#define L2LEN 1024
#define TOUT 128
#define NTILES (L2LEN / TOUT)

// bf16 tile strides (elements)
#define ASTR 200      // A rows: 128 x 192 (stride 200 -> conflict-free LDSM)
#define BSTR 200      // B rows: 64 x 192

// smem byte offsets (k_expert)
#define A_HI_OFF 0                         // 128*200*2 = 51200
#define A_LO_OFF (A_HI_OFF + 51200)        // 51200
#define B_HI_OFF (A_LO_OFF + 51200)        // 64*200*2 = 25600
#define B_LO_OFF (B_HI_OFF + 25600)        // 25600
#define XS_OFF   (B_LO_OFF + 25600)        // 520 floats = 2080
#define WAS_OFF  (XS_OFF + 2080)           // 448 floats = 1792
#define BAS_OFF  (WAS_OFF + 1792)          // 64 floats
#define BBS_OFF  (BAS_OFF + 256)           // 64 floats
#define SMEM_BYTES (BBS_OFF + 256)

// scratch
__device__ float g_mag[NB * NFRAMES * NBINS];
__device__ int   g_eidx[NB * 2];
__device__ float g_ew[NB * 2];

__device__ __forceinline__ uint32_t smem_u32(const void* p) {
    uint32_t a;
    asm("{ .reg .u64 t; cvta.to.shared.u64 t, %1; cvt.u32.u64 %0, t; }"
        : "=r"(a) : "l"(p));
    return a;
}
__device__ __forceinline__ void ldsm_x4(uint32_t& r0, uint32_t& r1,
                                        uint32_t& r2, uint32_t& r3,
                                        uint32_t addr) {
    asm volatile("ldmatrix.sync.aligned.m8n8.x4.shared.b16 {%0,%1,%2,%3}, [%4];"
                 : "=r"(r0), "=r"(r1), "=r"(r2), "=r"(r3) : "r"(addr));
}
__device__ __forceinline__ void mma16816(float* d, const uint32_t* a,
                                         uint32_t b0, uint32_t b1) {
    asm volatile(
        "mma.sync.aligned.m16n8k16.row.col.f32.bf16.bf16.f32 "
        "{%0,%1,%2,%3}, {%4,%5,%6,%7}, {%8,%9}, {%0,%1,%2,%3};"
        : "+f"(d[0]), "+f"(d[1]), "+f"(d[2]), "+f"(d[3])
        : "r"(a[0]), "r"(a[1]), "r"(a[2]), "r"(a[3]), "r"(b0), "r"(b1));
}

// ---------------------------------------------------------------------------
// Kernel 1: STFT magnitudes (phasor recurrence)
// ---------------------------------------------------------------------------
__global__ void __launch_bounds__(128) k_stft(const float* __restrict__ x) {
    __shared__ float f[NFFT];
    const int fr = blockIdx.x, b = blockIdx.y, t = threadIdx.x;
    for (int i = t; i < NFFT; i += 128) {
        int m = fr * HOP + i - 128;
        if (m < 0) m = -m;
        else if (m >= NSAMP) m = 2 * NSAMP - 2 - m;
        const float win = 0.5f - 0.5f * cospif((float)i / 128.0f);
        f[i] = x[b * NSAMP + m] * win;
    }
    __syncthreads();
    float* magp = &g_mag[(b * NFRAMES + fr) * NBINS];
    if (t == 0) {
        float s0 = 0.f, s1 = 0.f;
#pragma unroll 8
        for (int n = 0; n < NFFT; n += 2) { s0 += f[n]; s1 += f[n + 1]; }
        magp[0] = fabsf(s0 + s1);
        magp[128] = fabsf(s0 - s1);
    } else {
        const float ang = (float)t / 128.0f;
        float c[4], s[4];
#pragma unroll
        for (int i = 0; i < 4; i++) { c[i] = cospif(ang * i); s[i] = sinpif(ang * i); }
        const float cD = cospif(ang * 4.0f), sD = sinpif(ang * 4.0f);
        float re_[4] = {0, 0, 0, 0}, im_[4] = {0, 0, 0, 0};
#pragma unroll 4
        for (int n4 = 0; n4 < 64; n4++) {
#pragma unroll
            for (int i = 0; i < 4; i++) {
                const float v = f[n4 * 4 + i];
                re_[i] += v * c[i]; im_[i] += v * s[i];
                const float cn = c[i] * cD - s[i] * sD;
                s[i] = c[i] * sD + s[i] * cD; c[i] = cn;
            }
        }
        const float re = (re_[0] + re_[1]) + (re_[2] + re_[3]);
        const float im = (im_[0] + im_[1]) + (im_[2] + im_[3]);
        magp[t] = sqrtf(re * re + im * im);
    }
}

// ---------------------------------------------------------------------------
// Kernel 2: pooling + gating MLP + top-2 + softmax
// ---------------------------------------------------------------------------
__global__ void __launch_bounds__(256) k_gate(
    const float* __restrict__ Wg1, const float* __restrict__ bg1,
    const float* __restrict__ Wg2, const float* __restrict__ bg2,
    const float* __restrict__ Wg3, const float* __restrict__ bg3) {
    __shared__ float p[NBINS]; __shared__ float h1[256];
    __shared__ float h2[128];  __shared__ float lg[NE];
    const int b = blockIdx.x, t = threadIdx.x;
    if (t < NBINS) {
        float s = 0.f;
        for (int fr = 0; fr < NFRAMES; fr++) s += g_mag[(b * NFRAMES + fr) * NBINS + t];
        p[t] = s * (1.0f / NFRAMES);
    }
    __syncthreads();
    { float s = bg1[t];
      for (int i = 0; i < NBINS; i++) s += p[i] * Wg1[i * 256 + t];
      h1[t] = fmaxf(s, 0.f); }
    __syncthreads();
    if (t < 128) {
        float s = bg2[t];
        for (int i = 0; i < 256; i++) s += h1[i] * Wg2[i * 128 + t];
        h2[t] = fmaxf(s, 0.f);
    }
    __syncthreads();
    if (t < NE) {
        float s = bg3[t];
        for (int i = 0; i < 128; i++) s += h2[i] * Wg3[i * NE + t];
        lg[t] = s;
    }
    __syncthreads();
    if (t == 0) {
        int i0 = 0; float v0 = lg[0];
        for (int j = 1; j < NE; j++) if (lg[j] > v0) { v0 = lg[j]; i0 = j; }
        int i1 = (i0 == 0) ? 1 : 0; float v1 = lg[i1];
        for (int j = 0; j < NE; j++) if (j != i0 && lg[j] > v1) { v1 = lg[j]; i1 = j; }
        const float e = expf(v1 - v0);
        const float inv = 1.f / (1.f + e);
        g_eidx[b * 2] = i0; g_eidx[b * 2 + 1] = i1;
        g_ew[b * 2] = inv;  g_ew[b * 2 + 1] = e * inv;
    }
}

// ---------------------------------------------------------------------------
// Kernel 3: fused top-2 expert conv stack via mma.sync bf16 (HMMA).
// grid (NTILES, 3, NB), 256 threads, ~156KB smem, 1 CTA/SM.
// Per expert: conv1 -> im2col A (hi/lo bf16 split), conv2 weights -> B (split);
// D[128t,64c] = Ah*Bh + Ah*Bl + Al*Bh, fp32 accum in registers;
// each warp: 16 t-rows x 64 ch (8 n-tiles), K=192 (12 k16 steps).
// Epilogue: bias+relu+gate-weight in regs; smem-transposed coalesced stores.
// ---------------------------------------------------------------------------
__global__ void __launch_bounds__(256) k_expert(
    float* __restrict__ out, const float* __restrict__ x,
    const float* __restrict__ wa3, const float* __restrict__ ba3,
    const float* __restrict__ wb3, const float* __restrict__ bb3,
    const float* __restrict__ wa5, const float* __restrict__ ba5,
    const float* __restrict__ wb5, const float* __restrict__ bb5,
    const float* __restrict__ wa7, const float* __restrict__ ba7,
    const float* __restrict__ wb7, const float* __restrict__ bb7) {
    extern __shared__ char smem[];
    const uint32_t sb = smem_u32(smem);
    float* xs  = (float*)(smem + XS_OFF);
    float* was = (float*)(smem + WAS_OFF);
    float* bas = (float*)(smem + BAS_OFF);
    float* bbs = (float*)(smem + BBS_OFF);

    const int tid  = threadIdx.x;
    const int wid  = tid >> 5;
    const int lane = tid & 31;
    const int tile = blockIdx.x, br = blockIdx.y, b = blockIdx.z;
    const int t0   = tile * TOUT;
    const int ksz  = 3 + 2 * br;
    const int pad  = ksz >> 1;

    const float* wap = (br == 0) ? wa3 : ((br == 1) ? wa5 : wa7);
    const float* bap = (br == 0) ? ba3 : ((br == 1) ? ba5 : ba7);
    const float* wbp = (br == 0) ? wb3 : ((br == 1) ? wb5 : wb7);
    const float* bbp = (br == 0) ? bb3 : ((br == 1) ? bb5 : bb7);

    const int   eidx[2] = { g_eidx[b * 2], g_eidx[b * 2 + 1] };
    const float ewgt[2] = { g_ew[b * 2],   g_ew[b * 2 + 1] };

    // stage x window: xi in [4*t0-5, 4*t0+514]
    const int xlo = 4 * t0 - 5;
    for (int i = tid; i < 520; i += 256) {
        const int xi = xlo + i;
        xs[i] = (xi >= 0 && xi < NSAMP) ? x[b * NSAMP + xi] : 0.f;
    }

    // per-lane ldmatrix address offsets (bytes, k0 added per step)
    const uint32_t aoff = (uint32_t)(((wid * 16 + (lane & 15)) * ASTR +
                                      ((lane & 16) ? 8 : 0)) * 2);
    const int brow = (lane & 7) + ((lane >> 1) & 8);   // row within 16-row pair
    const int bko  = (lane & 8) ? 8 : 0;
    uint32_t boff[4];
#pragma unroll
    for (int ng = 0; ng < 4; ng++)
        boff[ng] = (uint32_t)(((ng * 16 + brow) * BSTR + bko) * 2);

    float facc[32];
#pragma unroll
    for (int i = 0; i < 32; i++) facc[i] = 0.f;

    for (int ei = 0; ei < 2; ei++) {
        const int e = eidx[ei];
        const float wgt = ewgt[ei];
        __syncthreads();   // xs ready / previous expert's tiles fully consumed

        // stage conv1 weights/biases
        for (int i = tid; i < CH * ksz; i += 256) was[i] = wap[e * CH * ksz + i];
        if (tid < CH) { bas[tid] = bap[e * CH + tid]; bbs[tid] = bbp[e * CH + tid]; }
        // conv2 weights -> hi/lo bf16 B tiles [c][kk]
        const float* wb = wbp + e * (CH * 192);
        for (int idx = tid; idx < CH * 192; idx += 256) {
            const int c = idx / 192;
            const int kk = idx - c * 192;
            const float w = wb[idx];
            const __nv_bfloat16 hi = __float2bfloat16(w);
            const __nv_bfloat16 lo = __float2bfloat16(w - __bfloat162float(hi));
            const uint32_t off = (uint32_t)(c * BSTR + kk) * 2;
            *(__nv_bfloat16*)(smem + B_HI_OFF + off) = hi;
            *(__nv_bfloat16*)(smem + B_LO_OFF + off) = lo;
        }
        __syncthreads();

        // conv1 -> im2col A[t][kk=3*ci+k] hi/lo (each h position computed once)
        for (int idx = tid; idx < 257 * 64; idx += 256) {
            const int p_i = idx >> 6;          // 0..256
            const int ch  = idx & 63;
            const int p   = 2 * t0 - 1 + p_i;  // global conv1 position
            float s = bas[ch];
            const float* wr = &was[ch * ksz];
            const int off = 2 * p_i + 3 - pad;
            for (int q = 0; q < ksz; q++) s += wr[q] * xs[off + q];
            s = (p >= 0) ? fmaxf(s, 0.f) : 0.f;
            const __nv_bfloat16 hi = __float2bfloat16(s);
            const __nv_bfloat16 lo = __float2bfloat16(s - __bfloat162float(hi));
            if ((p_i & 1) == 0) {
                const int t = p_i >> 1;        // h[2t] -> kk 3ch+1 at row t? no:
                // p_i even: h at p = 2(t0+t) - 1 + 0? mapping: row t uses
                // kk = 3ch+k where h index p_i = 2t + k - 0 ... derived:
                // y[t] needs h[2t-1],h[2t],h[2t+1] -> p_i = 2t, 2t+1, 2t+2
                // k=1 -> p_i=2t+1 (odd); k=0 -> p_i=2t (even); k=2 -> p_i=2t+2
                if (t < 128) {   // k=0 for row t
                    const uint32_t o = (uint32_t)(t * ASTR + 3 * ch + 0) * 2;
                    *(__nv_bfloat16*)(smem + A_HI_OFF + o) = hi;
                    *(__nv_bfloat16*)(smem + A_LO_OFF + o) = lo;
                }
                if (t >= 1) {    // k=2 for row t-1
                    const uint32_t o = (uint32_t)((t - 1) * ASTR + 3 * ch + 2) * 2;
                    *(__nv_bfloat16*)(smem + A_HI_OFF + o) = hi;
                    *(__nv_bfloat16*)(smem + A_LO_OFF + o) = lo;
                }
            } else {             // k=1 for row (p_i-1)/2
                const uint32_t o = (uint32_t)(((p_i - 1) >> 1) * ASTR + 3 * ch + 1) * 2;
                *(__nv_bfloat16*)(smem + A_HI_OFF + o) = hi;
                *(__nv_bfloat16*)(smem + A_LO_OFF + o) = lo;
            }
        }
        __syncthreads();

        // GEMM: 8 n-tiles x 12 k-steps x 3 passes
        float acc[32];
#pragma unroll
        for (int i = 0; i < 32; i++) acc[i] = 0.f;

        for (int ks = 0; ks < 12; ks++) {
            const uint32_t kb = (uint32_t)(ks * 16 * 2);
            uint32_t ah[4], al[4];
            ldsm_x4(ah[0], ah[1], ah[2], ah[3], sb + A_HI_OFF + aoff + kb);
            ldsm_x4(al[0], al[1], al[2], al[3], sb + A_LO_OFF + aoff + kb);
#pragma unroll
            for (int ng = 0; ng < 4; ng++) {
                uint32_t bh[4], bl[4];
                ldsm_x4(bh[0], bh[1], bh[2], bh[3], sb + B_HI_OFF + boff[ng] + kb);
                ldsm_x4(bl[0], bl[1], bl[2], bl[3], sb + B_LO_OFF + boff[ng] + kb);
                float* d0 = &acc[(2 * ng) * 4];
                float* d1 = &acc[(2 * ng + 1) * 4];
                mma16816(d0, ah, bh[0], bh[1]);
                mma16816(d1, ah, bh[2], bh[3]);
                mma16816(d0, ah, bl[0], bl[1]);
                mma16816(d1, ah, bl[2], bl[3]);
                mma16816(d0, al, bh[0], bh[1]);
                mma16816(d1, al, bh[2], bh[3]);
            }
        }

        // epilogue: bias + relu + gate-weighted accumulate
#pragma unroll
        for (int nt = 0; nt < 8; nt++) {
            const int c0 = nt * 8 + (lane & 3) * 2;
            const float b0 = bbs[c0], b1 = bbs[c0 + 1];
            facc[nt * 4 + 0] += wgt * fmaxf(acc[nt * 4 + 0] + b0, 0.f);
            facc[nt * 4 + 1] += wgt * fmaxf(acc[nt * 4 + 1] + b1, 0.f);
            facc[nt * 4 + 2] += wgt * fmaxf(acc[nt * 4 + 2] + b0, 0.f);
            facc[nt * 4 + 3] += wgt * fmaxf(acc[nt * 4 + 3] + b1, 0.f);
        }
    }

    // transpose via smem (reuse A region) then coalesced stores
    __syncthreads();   // all warps done reading A/B tiles
    float* stage = (float*)(smem + A_HI_OFF) + wid * (64 * 17);
    {
        const int rt = lane >> 2;            // row 0..7
#pragma unroll
        for (int nt = 0; nt < 8; nt++) {
            const int c0 = nt * 8 + (lane & 3) * 2;
            stage[(c0    ) * 17 + rt]     = facc[nt * 4 + 0];
            stage[(c0 + 1) * 17 + rt]     = facc[nt * 4 + 1];
            stage[(c0    ) * 17 + rt + 8] = facc[nt * 4 + 2];
            stage[(c0 + 1) * 17 + rt + 8] = facc[nt * 4 + 3];
        }
    }
    __syncwarp();
    {
        const int tl = lane & 15;
        const size_t obase = (size_t)(b * 192 + br * 64) * L2LEN + t0 + wid * 16 + tl;
#pragma unroll
        for (int it = 0; it < 32; it++) {
            const int c = it * 2 + (lane >> 4);
            out[obase + (size_t)c * L2LEN] = stage[c * 17 + tl];
        }
    }
}

// ---------------------------------------------------------------------------
extern "C" void kernel_launch(void* const* d_in, const int* in_sizes, int n_in,
                              void* d_out, int out_size) {
    const float* x   = (const float*)d_in[0];
    const float* Wg1 = (const float*)d_in[1];
    const float* bg1 = (const float*)d_in[2];
    const float* Wg2 = (const float*)d_in[3];
    const float* bg2 = (const float*)d_in[4];
    const float* Wg3 = (const float*)d_in[5];
    const float* bg3 = (const float*)d_in[6];
    const float* wa3 = (const float*)d_in[7];
    const float* ba3 = (const float*)d_in[8];
    const float* wb3 = (const float*)d_in[9];
    const float* bb3 = (const float*)d_in[10];
    const float* wa5 = (const float*)d_in[11];
    const float* ba5 = (const float*)d_in[12];
    const float* wb5 = (const float*)d_in[13];
    const float* bb5 = (const float*)d_in[14];
    const float* wa7 = (const float*)d_in[15];
    const float* ba7 = (const float*)d_in[16];
    const float* wb7 = (const float*)d_in[17];
    const float* bb7 = (const float*)d_in[18];
    float* out = (float*)d_out;

    k_stft<<<dim3(NFRAMES, NB), 128>>>(x);
    k_gate<<<NB, 256>>>(Wg1, bg1, Wg2, bg2, Wg3, bg3);

    (void)cudaFuncSetAttribute(k_expert,
                               cudaFuncAttributeMaxDynamicSharedMemorySize,
                               SMEM_BYTES);
    k_expert<<<dim3(NTILES, 3, NB), 256, SMEM_BYTES>>>(
        out, x,
        wa3, ba3, wb3, bb3,
        wa5, ba5, wb5, bb5,
        wa7, ba7, wb7, bb7);
}

// round 10
// speedup vs baseline: 1.4027x; 1.0920x over previous
#include <cuda_runtime.h>
#include <cuda_fp16.h>
#include <math.h>
#include <stdint.h>

#define NSAMP 4096
#define NFFT 256
#define HOP 64
#define NFRAMES 65
#define NBINS 129
#define NB 64
#define NE 8
#define CH 64
#define L2LEN 1024
#define TOUT 128
#define NTILES (L2LEN / TOUT)

// fp16 tile strides (elements)
#define ASTR 200      // A rows: 128 x 192 (row stride 400 B -> conflict-free LDSM)
#define BSTR 200      // B rows: 64 x 192

// smem byte offsets (k_expert)
#define A_HI_OFF 0                         // 128*200*2 = 51200
#define A_LO_OFF (A_HI_OFF + 51200)        // 51200
#define B_OFF    (A_LO_OFF + 51200)        // 64*200*2 = 25600
#define XS_OFF   (B_OFF + 25600)           // 520 floats = 2080
#define WAS_OFF  (XS_OFF + 2080)           // 448 floats = 1792
#define BAS_OFF  (WAS_OFF + 1792)          // 64 floats (+pad)
#define BBS_OFF  (BAS_OFF + 256)
#define SMEM_BYTES (BBS_OFF + 256)         // 132384

// scratch
__device__ float g_mag[NB * NFRAMES * NBINS];
__device__ int   g_eidx[NB * 2];
__device__ float g_ew[NB * 2];
__device__ __align__(16) __half g_wb16[3 * NE * CH * BSTR];  // LDSM-ready fp16 weights

__device__ __forceinline__ uint32_t smem_u32(const void* p) {
    uint32_t a;
    asm("{ .reg .u64 t; cvta.to.shared.u64 t, %1; cvt.u32.u64 %0, t; }"
        : "=r"(a) : "l"(p));
    return a;
}
__device__ __forceinline__ void ldsm_x4(uint32_t& r0, uint32_t& r1,
                                        uint32_t& r2, uint32_t& r3,
                                        uint32_t addr) {
    asm volatile("ldmatrix.sync.aligned.m8n8.x4.shared.b16 {%0,%1,%2,%3}, [%4];"
                 : "=r"(r0), "=r"(r1), "=r"(r2), "=r"(r3) : "r"(addr));
}
__device__ __forceinline__ void mma16816(float* d, const uint32_t* a,
                                         uint32_t b0, uint32_t b1) {
    asm volatile(
        "mma.sync.aligned.m16n8k16.row.col.f32.f16.f16.f32 "
        "{%0,%1,%2,%3}, {%4,%5,%6,%7}, {%8,%9}, {%0,%1,%2,%3};"
        : "+f"(d[0]), "+f"(d[1]), "+f"(d[2]), "+f"(d[3])
        : "r"(a[0]), "r"(a[1]), "r"(a[2]), "r"(a[3]), "r"(b0), "r"(b1));
}

// ---------------------------------------------------------------------------
// Kernel 0: one-time conv2 weight conversion -> fp16 LDSM-ready tiles
// grid (3, NE), 256 threads
// ---------------------------------------------------------------------------
__global__ void __launch_bounds__(256) k_prep(
    const float* __restrict__ wb3, const float* __restrict__ wb5,
    const float* __restrict__ wb7) {
    const int br = blockIdx.x, e = blockIdx.y;
    const float* wb = ((br == 0) ? wb3 : (br == 1) ? wb5 : wb7) + e * CH * 192;
    __half* dst = g_wb16 + (br * NE + e) * (CH * BSTR);
    for (int idx = threadIdx.x; idx < CH * BSTR; idx += 256) {
        const int c = idx / BSTR;
        const int kk = idx - c * BSTR;
        dst[idx] = __float2half_rn((kk < 192) ? wb[c * 192 + kk] : 0.f);
    }
}

// ---------------------------------------------------------------------------
// Kernel 1: STFT magnitudes (phasor recurrence)
// ---------------------------------------------------------------------------
__global__ void __launch_bounds__(128) k_stft(const float* __restrict__ x) {
    __shared__ float f[NFFT];
    const int fr = blockIdx.x, b = blockIdx.y, t = threadIdx.x;
    for (int i = t; i < NFFT; i += 128) {
        int m = fr * HOP + i - 128;
        if (m < 0) m = -m;
        else if (m >= NSAMP) m = 2 * NSAMP - 2 - m;
        const float win = 0.5f - 0.5f * cospif((float)i / 128.0f);
        f[i] = x[b * NSAMP + m] * win;
    }
    __syncthreads();
    float* magp = &g_mag[(b * NFRAMES + fr) * NBINS];
    if (t == 0) {
        float s0 = 0.f, s1 = 0.f;
#pragma unroll 8
        for (int n = 0; n < NFFT; n += 2) { s0 += f[n]; s1 += f[n + 1]; }
        magp[0] = fabsf(s0 + s1);
        magp[128] = fabsf(s0 - s1);
    } else {
        const float ang = (float)t / 128.0f;
        float c[4], s[4];
#pragma unroll
        for (int i = 0; i < 4; i++) { c[i] = cospif(ang * i); s[i] = sinpif(ang * i); }
        const float cD = cospif(ang * 4.0f), sD = sinpif(ang * 4.0f);
        float re_[4] = {0, 0, 0, 0}, im_[4] = {0, 0, 0, 0};
#pragma unroll 4
        for (int n4 = 0; n4 < 64; n4++) {
#pragma unroll
            for (int i = 0; i < 4; i++) {
                const float v = f[n4 * 4 + i];
                re_[i] += v * c[i]; im_[i] += v * s[i];
                const float cn = c[i] * cD - s[i] * sD;
                s[i] = c[i] * sD + s[i] * cD; c[i] = cn;
            }
        }
        const float re = (re_[0] + re_[1]) + (re_[2] + re_[3]);
        const float im = (im_[0] + im_[1]) + (im_[2] + im_[3]);
        magp[t] = sqrtf(re * re + im * im);
    }
}

// ---------------------------------------------------------------------------
// Kernel 2: pooling + gating MLP + top-2 + softmax
// ---------------------------------------------------------------------------
__global__ void __launch_bounds__(256) k_gate(
    const float* __restrict__ Wg1, const float* __restrict__ bg1,
    const float* __restrict__ Wg2, const float* __restrict__ bg2,
    const float* __restrict__ Wg3, const float* __restrict__ bg3) {
    __shared__ float p[NBINS]; __shared__ float h1[256];
    __shared__ float h2[128];  __shared__ float lg[NE];
    const int b = blockIdx.x, t = threadIdx.x;
    if (t < NBINS) {
        float s = 0.f;
        for (int fr = 0; fr < NFRAMES; fr++) s += g_mag[(b * NFRAMES + fr) * NBINS + t];
        p[t] = s * (1.0f / NFRAMES);
    }
    __syncthreads();
    { float s = bg1[t];
      for (int i = 0; i < NBINS; i++) s += p[i] * Wg1[i * 256 + t];
      h1[t] = fmaxf(s, 0.f); }
    __syncthreads();
    if (t < 128) {
        float s = bg2[t];
        for (int i = 0; i < 256; i++) s += h1[i] * Wg2[i * 128 + t];
        h2[t] = fmaxf(s, 0.f);
    }
    __syncthreads();
    if (t < NE) {
        float s = bg3[t];
        for (int i = 0; i < 128; i++) s += h2[i] * Wg3[i * NE + t];
        lg[t] = s;
    }
    __syncthreads();
    if (t == 0) {
        int i0 = 0; float v0 = lg[0];
        for (int j = 1; j < NE; j++) if (lg[j] > v0) { v0 = lg[j]; i0 = j; }
        int i1 = (i0 == 0) ? 1 : 0; float v1 = lg[i1];
        for (int j = 0; j < NE; j++) if (j != i0 && lg[j] > v1) { v1 = lg[j]; i1 = j; }
        const float e = expf(v1 - v0);
        const float inv = 1.f / (1.f + e);
        g_eidx[b * 2] = i0; g_eidx[b * 2 + 1] = i1;
        g_ew[b * 2] = inv;  g_ew[b * 2 + 1] = e * inv;
    }
}

// ---------------------------------------------------------------------------
// Kernel 3: fused top-2 expert conv stack via mma.sync fp16 (HMMA), 2 passes.
// grid (NTILES, 3, NB), 256 threads, ~132KB smem.
// D[128t,64c] = (Ah + Al) * B  (A split fp16 hi/lo exact; B single fp16).
// ---------------------------------------------------------------------------
__global__ void __launch_bounds__(256) k_expert(
    float* __restrict__ out, const float* __restrict__ x,
    const float* __restrict__ wa3, const float* __restrict__ ba3,
    const float* __restrict__ bb3,
    const float* __restrict__ wa5, const float* __restrict__ ba5,
    const float* __restrict__ bb5,
    const float* __restrict__ wa7, const float* __restrict__ ba7,
    const float* __restrict__ bb7) {
    extern __shared__ char smem[];
    const uint32_t sb = smem_u32(smem);
    float* xs  = (float*)(smem + XS_OFF);
    float* was = (float*)(smem + WAS_OFF);
    float* bas = (float*)(smem + BAS_OFF);
    float* bbs = (float*)(smem + BBS_OFF);

    const int tid  = threadIdx.x;
    const int wid  = tid >> 5;
    const int lane = tid & 31;
    const int tile = blockIdx.x, br = blockIdx.y, b = blockIdx.z;
    const int t0   = tile * TOUT;
    const int ksz  = 3 + 2 * br;
    const int pad  = ksz >> 1;

    const float* wap = (br == 0) ? wa3 : ((br == 1) ? wa5 : wa7);
    const float* bap = (br == 0) ? ba3 : ((br == 1) ? ba5 : ba7);
    const float* bbp = (br == 0) ? bb3 : ((br == 1) ? bb5 : bb7);

    const int   eidx[2] = { g_eidx[b * 2], g_eidx[b * 2 + 1] };
    const float ewgt[2] = { g_ew[b * 2],   g_ew[b * 2 + 1] };

    // stage x window: xi in [4*t0-5, 4*t0+514]
    const int xlo = 4 * t0 - 5;
    for (int i = tid; i < 520; i += 256) {
        const int xi = xlo + i;
        xs[i] = (xi >= 0 && xi < NSAMP) ? x[b * NSAMP + xi] : 0.f;
    }

    // per-lane ldmatrix address offsets (bytes; + ks*32 per step)
    const uint32_t aoff = (uint32_t)(((wid * 16 + (lane & 15)) * ASTR +
                                      ((lane & 16) ? 8 : 0)) * 2);
    const int brow = (lane & 7) + ((lane >> 1) & 8);
    const int bko  = (lane & 8) ? 8 : 0;
    uint32_t boff[4];
#pragma unroll
    for (int ng = 0; ng < 4; ng++)
        boff[ng] = (uint32_t)(((ng * 16 + brow) * BSTR + bko) * 2);

    float facc[32];
#pragma unroll
    for (int i = 0; i < 32; i++) facc[i] = 0.f;

    for (int ei = 0; ei < 2; ei++) {
        const int e = eidx[ei];
        const float wgt = ewgt[ei];
        __syncthreads();   // xs ready / previous expert's tiles fully consumed

        // stage conv1 weights/biases
        for (int i = tid; i < CH * ksz; i += 256) was[i] = wap[e * CH * ksz + i];
        if (tid < CH) { bas[tid] = bap[e * CH + tid]; bbs[tid] = bbp[e * CH + tid]; }
        // stage precomputed fp16 B tile (pure 16B copy, 1600 uint4)
        {
            const uint4* src = (const uint4*)(g_wb16 + (br * NE + e) * (CH * BSTR));
            uint4* dst = (uint4*)(smem + B_OFF);
            for (int i = tid; i < (CH * BSTR * 2) / 16; i += 256) dst[i] = src[i];
        }
        __syncthreads();

        // conv1 -> im2col A[t][kk=3*ch+k], fp16 hi/lo (each h computed once)
        // y[t] needs h at p_i = 2t (k=0), 2t+1 (k=1), 2t+2 (k=2);
        // p_global = 2*t0 - 1 + p_i
        for (int idx = tid; idx < 257 * 64; idx += 256) {
            const int p_i = idx >> 6;
            const int ch  = idx & 63;
            const int p   = 2 * t0 - 1 + p_i;
            float s = bas[ch];
            const float* wr = &was[ch * ksz];
            const int off = 2 * p_i + 3 - pad;
            for (int q = 0; q < ksz; q++) s += wr[q] * xs[off + q];
            s = (p >= 0) ? fmaxf(s, 0.f) : 0.f;
            const __half hi = __float2half_rn(s);
            const __half lo = __float2half_rn(s - __half2float(hi));
            if ((p_i & 1) == 0) {
                const int t = p_i >> 1;
                if (t < 128) {
                    const uint32_t o = (uint32_t)(t * ASTR + 3 * ch + 0) * 2;
                    *(__half*)(smem + A_HI_OFF + o) = hi;
                    *(__half*)(smem + A_LO_OFF + o) = lo;
                }
                if (t >= 1) {
                    const uint32_t o = (uint32_t)((t - 1) * ASTR + 3 * ch + 2) * 2;
                    *(__half*)(smem + A_HI_OFF + o) = hi;
                    *(__half*)(smem + A_LO_OFF + o) = lo;
                }
            } else {
                const uint32_t o = (uint32_t)(((p_i - 1) >> 1) * ASTR + 3 * ch + 1) * 2;
                *(__half*)(smem + A_HI_OFF + o) = hi;
                *(__half*)(smem + A_LO_OFF + o) = lo;
            }
        }
        __syncthreads();

        // GEMM: 8 n-tiles x 12 k-steps x 2 passes
        float acc[32];
#pragma unroll
        for (int i = 0; i < 32; i++) acc[i] = 0.f;

        for (int ks = 0; ks < 12; ks++) {
            const uint32_t kb = (uint32_t)(ks * 32);
            uint32_t ah[4], al[4];
            ldsm_x4(ah[0], ah[1], ah[2], ah[3], sb + A_HI_OFF + aoff + kb);
            ldsm_x4(al[0], al[1], al[2], al[3], sb + A_LO_OFF + aoff + kb);
#pragma unroll
            for (int ng = 0; ng < 4; ng++) {
                uint32_t bh[4];
                ldsm_x4(bh[0], bh[1], bh[2], bh[3], sb + B_OFF + boff[ng] + kb);
                float* d0 = &acc[(2 * ng) * 4];
                float* d1 = &acc[(2 * ng + 1) * 4];
                mma16816(d0, ah, bh[0], bh[1]);
                mma16816(d1, ah, bh[2], bh[3]);
                mma16816(d0, al, bh[0], bh[1]);
                mma16816(d1, al, bh[2], bh[3]);
            }
        }

        // epilogue: bias + relu + gate-weighted accumulate
#pragma unroll
        for (int nt = 0; nt < 8; nt++) {
            const int c0 = nt * 8 + (lane & 3) * 2;
            const float b0 = bbs[c0], b1 = bbs[c0 + 1];
            facc[nt * 4 + 0] += wgt * fmaxf(acc[nt * 4 + 0] + b0, 0.f);
            facc[nt * 4 + 1] += wgt * fmaxf(acc[nt * 4 + 1] + b1, 0.f);
            facc[nt * 4 + 2] += wgt * fmaxf(acc[nt * 4 + 2] + b0, 0.f);
            facc[nt * 4 + 3] += wgt * fmaxf(acc[nt * 4 + 3] + b1, 0.f);
        }
    }

    // transpose via smem (reuse A region) then coalesced stores
    __syncthreads();
    float* stage = (float*)(smem + A_HI_OFF) + wid * (64 * 17);
    {
        const int rt = lane >> 2;
#pragma unroll
        for (int nt = 0; nt < 8; nt++) {
            const int c0 = nt * 8 + (lane & 3) * 2;
            stage[(c0    ) * 17 + rt]     = facc[nt * 4 + 0];
            stage[(c0 + 1) * 17 + rt]     = facc[nt * 4 + 1];
            stage[(c0    ) * 17 + rt + 8] = facc[nt * 4 + 2];
            stage[(c0 + 1) * 17 + rt + 8] = facc[nt * 4 + 3];
        }
    }
    __syncwarp();
    {
        const int tl = lane & 15;
        const size_t obase = (size_t)(b * 192 + br * 64) * L2LEN + t0 + wid * 16 + tl;
#pragma unroll
        for (int it = 0; it < 32; it++) {
            const int c = it * 2 + (lane >> 4);
            out[obase + (size_t)c * L2LEN] = stage[c * 17 + tl];
        }
    }
}

// ---------------------------------------------------------------------------
extern "C" void kernel_launch(void* const* d_in, const int* in_sizes, int n_in,
                              void* d_out, int out_size) {
    const float* x   = (const float*)d_in[0];
    const float* Wg1 = (const float*)d_in[1];
    const float* bg1 = (const float*)d_in[2];
    const float* Wg2 = (const float*)d_in[3];
    const float* bg2 = (const float*)d_in[4];
    const float* Wg3 = (const float*)d_in[5];
    const float* bg3 = (const float*)d_in[6];
    const float* wa3 = (const float*)d_in[7];
    const float* ba3 = (const float*)d_in[8];
    const float* wb3 = (const float*)d_in[9];
    const float* bb3 = (const float*)d_in[10];
    const float* wa5 = (const float*)d_in[11];
    const float* ba5 = (const float*)d_in[12];
    const float* wb5 = (const float*)d_in[13];
    const float* bb5 = (const float*)d_in[14];
    const float* wa7 = (const float*)d_in[15];
    const float* ba7 = (const float*)d_in[16];
    const float* wb7 = (const float*)d_in[17];
    const float* bb7 = (const float*)d_in[18];
    float* out = (float*)d_out;

    k_prep<<<dim3(3, NE), 256>>>(wb3, wb5, wb7);
    k_stft<<<dim3(NFRAMES, NB), 128>>>(x);
    k_gate<<<NB, 256>>>(Wg1, bg1, Wg2, bg2, Wg3, bg3);

    (void)cudaFuncSetAttribute(k_expert,
                               cudaFuncAttributeMaxDynamicSharedMemorySize,
                               SMEM_BYTES);
    k_expert<<<dim3(NTILES, 3, NB), 256, SMEM_BYTES>>>(
        out, x,
        wa3, ba3, bb3,
        wa5, ba5, bb5,
        wa7, ba7, bb7);
}

// round 11
// speedup vs baseline: 2.7298x; 1.9460x over previous
#include <cuda_runtime.h>
#include <cuda_fp16.h>
#include <math.h>
#include <stdint.h>

#define NSAMP 4096
#define NFFT 256
#define HOP 64
#define NFRAMES 65
#define NBINS 129
#define NB 64
#define NE 8
#define CH 64
#define L2LEN 1024
#define TOUT 64
#define NTILES (L2LEN / TOUT)

#define ASTR 200      // fp16 row stride (400 B -> conflict-free LDSM)
#define BSTR 200

// smem byte offsets (k_expert)
#define A_OFF  0                       // 64*200*2 = 25600
#define B_OFF  25600                   // 64*200*2 = 25600
#define XS_OFF 51200                   // 272 floats = 1088
#define WAS_OFF (XS_OFF + 1088)        // 448 floats = 1792
#define BAS_OFF (WAS_OFF + 1792)       // 64 floats (+pad)
#define BBS_OFF (BAS_OFF + 256)
#define SMEM_BYTES (BBS_OFF + 256)     // 54592 -> 4 CTAs/SM

// scratch
__device__ float g_mag[NB * NFRAMES * NBINS];
__device__ int   g_eidx[NB * 2];
__device__ float g_ew[NB * 2];
__device__ __align__(16) __half g_wb16[3 * NE * CH * BSTR];

__device__ __forceinline__ uint32_t smem_u32(const void* p) {
    uint32_t a;
    asm("{ .reg .u64 t; cvta.to.shared.u64 t, %1; cvt.u32.u64 %0, t; }"
        : "=r"(a) : "l"(p));
    return a;
}
__device__ __forceinline__ void ldsm_x4(uint32_t& r0, uint32_t& r1,
                                        uint32_t& r2, uint32_t& r3,
                                        uint32_t addr) {
    asm volatile("ldmatrix.sync.aligned.m8n8.x4.shared.b16 {%0,%1,%2,%3}, [%4];"
                 : "=r"(r0), "=r"(r1), "=r"(r2), "=r"(r3) : "r"(addr));
}
__device__ __forceinline__ void mma16816(float* d, const uint32_t* a,
                                         uint32_t b0, uint32_t b1) {
    asm volatile(
        "mma.sync.aligned.m16n8k16.row.col.f32.f16.f16.f32 "
        "{%0,%1,%2,%3}, {%4,%5,%6,%7}, {%8,%9}, {%0,%1,%2,%3};"
        : "+f"(d[0]), "+f"(d[1]), "+f"(d[2]), "+f"(d[3])
        : "r"(a[0]), "r"(a[1]), "r"(a[2]), "r"(a[3]), "r"(b0), "r"(b1));
}

// ---------------------------------------------------------------------------
// Kernel 0: conv2 weights -> fp16 LDSM-ready tiles. grid (3, NE)
// ---------------------------------------------------------------------------
__global__ void __launch_bounds__(256) k_prep(
    const float* __restrict__ wb3, const float* __restrict__ wb5,
    const float* __restrict__ wb7) {
    const int br = blockIdx.x, e = blockIdx.y;
    const float* wb = ((br == 0) ? wb3 : (br == 1) ? wb5 : wb7) + e * CH * 192;
    __half* dst = g_wb16 + (br * NE + e) * (CH * BSTR);
    for (int idx = threadIdx.x; idx < CH * BSTR; idx += 256) {
        const int c = idx / BSTR;
        const int kk = idx - c * BSTR;
        dst[idx] = __float2half_rn((kk < 192) ? wb[c * 192 + kk] : 0.f);
    }
}

// ---------------------------------------------------------------------------
// Kernel 1: STFT magnitudes (phasor recurrence)
// ---------------------------------------------------------------------------
__global__ void __launch_bounds__(128) k_stft(const float* __restrict__ x) {
    __shared__ float f[NFFT];
    const int fr = blockIdx.x, b = blockIdx.y, t = threadIdx.x;
    for (int i = t; i < NFFT; i += 128) {
        int m = fr * HOP + i - 128;
        if (m < 0) m = -m;
        else if (m >= NSAMP) m = 2 * NSAMP - 2 - m;
        const float win = 0.5f - 0.5f * cospif((float)i / 128.0f);
        f[i] = x[b * NSAMP + m] * win;
    }
    __syncthreads();
    float* magp = &g_mag[(b * NFRAMES + fr) * NBINS];
    if (t == 0) {
        float s0 = 0.f, s1 = 0.f;
#pragma unroll 8
        for (int n = 0; n < NFFT; n += 2) { s0 += f[n]; s1 += f[n + 1]; }
        magp[0] = fabsf(s0 + s1);
        magp[128] = fabsf(s0 - s1);
    } else {
        const float ang = (float)t / 128.0f;
        float c[4], s[4];
#pragma unroll
        for (int i = 0; i < 4; i++) { c[i] = cospif(ang * i); s[i] = sinpif(ang * i); }
        const float cD = cospif(ang * 4.0f), sD = sinpif(ang * 4.0f);
        float re_[4] = {0, 0, 0, 0}, im_[4] = {0, 0, 0, 0};
#pragma unroll 4
        for (int n4 = 0; n4 < 64; n4++) {
#pragma unroll
            for (int i = 0; i < 4; i++) {
                const float v = f[n4 * 4 + i];
                re_[i] += v * c[i]; im_[i] += v * s[i];
                const float cn = c[i] * cD - s[i] * sD;
                s[i] = c[i] * sD + s[i] * cD; c[i] = cn;
            }
        }
        const float re = (re_[0] + re_[1]) + (re_[2] + re_[3]);
        const float im = (im_[0] + im_[1]) + (im_[2] + im_[3]);
        magp[t] = sqrtf(re * re + im * im);
    }
}

// ---------------------------------------------------------------------------
// Kernel 2: pooling + gating MLP + top-2 + softmax
// ---------------------------------------------------------------------------
__global__ void __launch_bounds__(256) k_gate(
    const float* __restrict__ Wg1, const float* __restrict__ bg1,
    const float* __restrict__ Wg2, const float* __restrict__ bg2,
    const float* __restrict__ Wg3, const float* __restrict__ bg3) {
    __shared__ float p[NBINS]; __shared__ float h1[256];
    __shared__ float h2[128];  __shared__ float lg[NE];
    const int b = blockIdx.x, t = threadIdx.x;
    if (t < NBINS) {
        float s = 0.f;
        for (int fr = 0; fr < NFRAMES; fr++) s += g_mag[(b * NFRAMES + fr) * NBINS + t];
        p[t] = s * (1.0f / NFRAMES);
    }
    __syncthreads();
    { float s = bg1[t];
      for (int i = 0; i < NBINS; i++) s += p[i] * Wg1[i * 256 + t];
      h1[t] = fmaxf(s, 0.f); }
    __syncthreads();
    if (t < 128) {
        float s = bg2[t];
        for (int i = 0; i < 256; i++) s += h1[i] * Wg2[i * 128 + t];
        h2[t] = fmaxf(s, 0.f);
    }
    __syncthreads();
    if (t < NE) {
        float s = bg3[t];
        for (int i = 0; i < 128; i++) s += h2[i] * Wg3[i * NE + t];
        lg[t] = s;
    }
    __syncthreads();
    if (t == 0) {
        int i0 = 0; float v0 = lg[0];
        for (int j = 1; j < NE; j++) if (lg[j] > v0) { v0 = lg[j]; i0 = j; }
        int i1 = (i0 == 0) ? 1 : 0; float v1 = lg[i1];
        for (int j = 0; j < NE; j++) if (j != i0 && lg[j] > v1) { v1 = lg[j]; i1 = j; }
        const float e = expf(v1 - v0);
        const float inv = 1.f / (1.f + e);
        g_eidx[b * 2] = i0; g_eidx[b * 2 + 1] = i1;
        g_ew[b * 2] = inv;  g_ew[b * 2 + 1] = e * inv;
    }
}

// ---------------------------------------------------------------------------
// Kernel 3: fused top-2 expert conv stack, fp16 HMMA, high occupancy.
// grid (16, 3, NB), 256 threads, 54.6KB smem -> 4 CTAs/SM.
// Warp wid: tg = wid>>1 owns t-rows [16tg,16tg+16); ch0 = (wid&1)*32.
// Per warp: A 16x192 (1 LDSM/ks), B 32ch (2 LDSM/ks), 4 MMA/ks, 12 ks.
// ---------------------------------------------------------------------------
__global__ void __launch_bounds__(256, 4) k_expert(
    float* __restrict__ out, const float* __restrict__ x,
    const float* __restrict__ wa3, const float* __restrict__ ba3,
    const float* __restrict__ bb3,
    const float* __restrict__ wa5, const float* __restrict__ ba5,
    const float* __restrict__ bb5,
    const float* __restrict__ wa7, const float* __restrict__ ba7,
    const float* __restrict__ bb7) {
    extern __shared__ char smem[];
    const uint32_t sb = smem_u32(smem);
    float* xs  = (float*)(smem + XS_OFF);
    float* was = (float*)(smem + WAS_OFF);
    float* bas = (float*)(smem + BAS_OFF);
    float* bbs = (float*)(smem + BBS_OFF);

    const int tid  = threadIdx.x;
    const int wid  = tid >> 5;
    const int lane = tid & 31;
    const int tile = blockIdx.x, br = blockIdx.y, b = blockIdx.z;
    const int t0   = tile * TOUT;
    const int ksz  = 3 + 2 * br;
    const int pad  = ksz >> 1;
    const int tg   = wid >> 1;
    const int ch0  = (wid & 1) * 32;

    const float* wap = (br == 0) ? wa3 : ((br == 1) ? wa5 : wa7);
    const float* bap = (br == 0) ? ba3 : ((br == 1) ? ba5 : ba7);
    const float* bbp = (br == 0) ? bb3 : ((br == 1) ? bb5 : bb7);

    const int   eidx[2] = { g_eidx[b * 2], g_eidx[b * 2 + 1] };
    const float ewgt[2] = { g_ew[b * 2],   g_ew[b * 2 + 1] };

    // stage x window: xi in [4*t0-5, 4*t0+266]
    const int xlo = 4 * t0 - 5;
    for (int i = tid; i < 272; i += 256) {
        const int xi = xlo + i;
        xs[i] = (xi >= 0 && xi < NSAMP) ? x[b * NSAMP + xi] : 0.f;
    }

    // ldmatrix lane offsets (bytes; + ks*32 added per k-step)
    const uint32_t aoff = (uint32_t)(((tg * 16 + (lane & 15)) * ASTR +
                                      ((lane & 16) ? 8 : 0)) * 2);
    const int brow = (lane & 7) + ((lane >> 1) & 8);
    const int bko  = (lane & 8) ? 8 : 0;
    const uint32_t boff0 = (uint32_t)(((ch0 + brow) * BSTR + bko) * 2);
    const uint32_t boff1 = (uint32_t)(((ch0 + 16 + brow) * BSTR + bko) * 2);

    float facc[16];
#pragma unroll
    for (int i = 0; i < 16; i++) facc[i] = 0.f;

    for (int ei = 0; ei < 2; ei++) {
        const int e = eidx[ei];
        const float wgt = ewgt[ei];
        __syncthreads();

        // stage conv1 weights/biases
        for (int i = tid; i < CH * ksz; i += 256) was[i] = wap[e * CH * ksz + i];
        if (tid < CH) { bas[tid] = bap[e * CH + tid]; bbs[tid] = bbp[e * CH + tid]; }
        // stage fp16 B tile (1600 uint4)
        {
            const uint4* src = (const uint4*)(g_wb16 + (br * NE + e) * (CH * BSTR));
            uint4* dst = (uint4*)(smem + B_OFF);
            for (int i = tid; i < (CH * BSTR * 2) / 16; i += 256) dst[i] = src[i];
        }
        __syncthreads();

        // conv1 -> im2col A[t'][kk=3*ch+k] fp16 (each h position computed once)
        // y[t'] needs p_i = 2t' (k=0), 2t'+1 (k=1), 2t'+2 (k=2); p_i in [0,128]
        for (int idx = tid; idx < 129 * 64; idx += 256) {
            const int p_i = idx >> 6;
            const int ch  = idx & 63;
            const int p   = 2 * t0 - 1 + p_i;
            float s = bas[ch];
            const float* wr = &was[ch * ksz];
            const int off = 2 * p_i + 3 - pad;
            for (int q = 0; q < ksz; q++) s += wr[q] * xs[off + q];
            s = (p >= 0) ? fmaxf(s, 0.f) : 0.f;
            const __half hv = __float2half_rn(s);
            if ((p_i & 1) == 0) {
                const int t = p_i >> 1;
                if (t < TOUT)
                    *(__half*)(smem + A_OFF + (uint32_t)(t * ASTR + 3 * ch + 0) * 2) = hv;
                if (t >= 1)
                    *(__half*)(smem + A_OFF + (uint32_t)((t - 1) * ASTR + 3 * ch + 2) * 2) = hv;
            } else {
                *(__half*)(smem + A_OFF + (uint32_t)(((p_i - 1) >> 1) * ASTR + 3 * ch + 1) * 2) = hv;
            }
        }
        __syncthreads();

        // GEMM: 12 k-steps, 4 MMA each
        float acc[16];
#pragma unroll
        for (int i = 0; i < 16; i++) acc[i] = 0.f;

        for (int ks = 0; ks < 12; ks++) {
            const uint32_t kb = (uint32_t)(ks * 32);
            uint32_t a[4], b0[4], b1[4];
            ldsm_x4(a[0], a[1], a[2], a[3], sb + A_OFF + aoff + kb);
            ldsm_x4(b0[0], b0[1], b0[2], b0[3], sb + B_OFF + boff0 + kb);
            ldsm_x4(b1[0], b1[1], b1[2], b1[3], sb + B_OFF + boff1 + kb);
            mma16816(&acc[0],  a, b0[0], b0[1]);
            mma16816(&acc[4],  a, b0[2], b0[3]);
            mma16816(&acc[8],  a, b1[0], b1[1]);
            mma16816(&acc[12], a, b1[2], b1[3]);
        }

        // epilogue: bias + relu + gate-weighted accumulate
#pragma unroll
        for (int nt = 0; nt < 4; nt++) {
            const int c0 = ch0 + nt * 8 + (lane & 3) * 2;
            const float b0 = bbs[c0], b1 = bbs[c0 + 1];
            facc[nt * 4 + 0] += wgt * fmaxf(acc[nt * 4 + 0] + b0, 0.f);
            facc[nt * 4 + 1] += wgt * fmaxf(acc[nt * 4 + 1] + b1, 0.f);
            facc[nt * 4 + 2] += wgt * fmaxf(acc[nt * 4 + 2] + b0, 0.f);
            facc[nt * 4 + 3] += wgt * fmaxf(acc[nt * 4 + 3] + b1, 0.f);
        }
    }

    // transpose via smem (reuse A region) then coalesced stores
    __syncthreads();
    float* stage = (float*)(smem + A_OFF) + wid * (32 * 17);
    {
        const int rt = lane >> 2;
#pragma unroll
        for (int nt = 0; nt < 4; nt++) {
            const int cl = nt * 8 + (lane & 3) * 2;   // local channel 0..31
            stage[(cl    ) * 17 + rt]     = facc[nt * 4 + 0];
            stage[(cl + 1) * 17 + rt]     = facc[nt * 4 + 1];
            stage[(cl    ) * 17 + rt + 8] = facc[nt * 4 + 2];
            stage[(cl + 1) * 17 + rt + 8] = facc[nt * 4 + 3];
        }
    }
    __syncwarp();
    {
        const int tl = lane & 15;
        const size_t obase = (size_t)(b * 192 + br * 64 + ch0) * L2LEN +
                             t0 + tg * 16 + tl;
#pragma unroll
        for (int it = 0; it < 16; it++) {
            const int cl = it * 2 + (lane >> 4);
            out[obase + (size_t)cl * L2LEN] = stage[cl * 17 + tl];
        }
    }
}

// ---------------------------------------------------------------------------
extern "C" void kernel_launch(void* const* d_in, const int* in_sizes, int n_in,
                              void* d_out, int out_size) {
    const float* x   = (const float*)d_in[0];
    const float* Wg1 = (const float*)d_in[1];
    const float* bg1 = (const float*)d_in[2];
    const float* Wg2 = (const float*)d_in[3];
    const float* bg2 = (const float*)d_in[4];
    const float* Wg3 = (const float*)d_in[5];
    const float* bg3 = (const float*)d_in[6];
    const float* wa3 = (const float*)d_in[7];
    const float* ba3 = (const float*)d_in[8];
    const float* wb3 = (const float*)d_in[9];
    const float* bb3 = (const float*)d_in[10];
    const float* wa5 = (const float*)d_in[11];
    const float* ba5 = (const float*)d_in[12];
    const float* wb5 = (const float*)d_in[13];
    const float* bb5 = (const float*)d_in[14];
    const float* wa7 = (const float*)d_in[15];
    const float* ba7 = (const float*)d_in[16];
    const float* wb7 = (const float*)d_in[17];
    const float* bb7 = (const float*)d_in[18];
    float* out = (float*)d_out;

    k_prep<<<dim3(3, NE), 256>>>(wb3, wb5, wb7);
    k_stft<<<dim3(NFRAMES, NB), 128>>>(x);
    k_gate<<<NB, 256>>>(Wg1, bg1, Wg2, bg2, Wg3, bg3);

    (void)cudaFuncSetAttribute(k_expert,
                               cudaFuncAttributeMaxDynamicSharedMemorySize,
                               SMEM_BYTES);
    k_expert<<<dim3(NTILES, 3, NB), 256, SMEM_BYTES>>>(
        out, x,
        wa3, ba3, bb3,
        wa5, ba5, bb5,
        wa7, ba7, bb7);
}

// round 12
// speedup vs baseline: 3.9028x; 1.4297x over previous
#include <cuda_runtime.h>
#include <cuda_fp16.h>
#include <math.h>
#include <stdint.h>

#define NSAMP 4096
#define NFFT 256
#define HOP 64
#define NFRAMES 65
#define NBINS 129
#define NB 64
#define NE 8
#define CH 64
#define L2LEN 1024
#define TOUT 64
#define NTILES (L2LEN / TOUT)

#define ASTR 200      // fp16 row stride (400 B -> conflict-free LDSM)
#define BSTR 200

// smem byte offsets (k_expert)
#define A_OFF  0                       // 64*200*2 = 25600
#define B_OFF  25600                   // 64*200*2 = 25600
#define XS_OFF 51200                   // 272 floats = 1088
#define SMEM_BYTES (XS_OFF + 1088)     // 52288 -> 4 CTAs/SM

// scratch
__device__ float g_mag[NB * NFRAMES * NBINS];
__device__ int   g_eidx[NB * 2];
__device__ float g_ew[NB * 2];
__device__ __align__(16) __half g_wb16[3 * NE * CH * BSTR];

__device__ __forceinline__ uint32_t smem_u32(const void* p) {
    uint32_t a;
    asm("{ .reg .u64 t; cvta.to.shared.u64 t, %1; cvt.u32.u64 %0, t; }"
        : "=r"(a) : "l"(p));
    return a;
}
__device__ __forceinline__ void ldsm_x4(uint32_t& r0, uint32_t& r1,
                                        uint32_t& r2, uint32_t& r3,
                                        uint32_t addr) {
    asm volatile("ldmatrix.sync.aligned.m8n8.x4.shared.b16 {%0,%1,%2,%3}, [%4];"
                 : "=r"(r0), "=r"(r1), "=r"(r2), "=r"(r3) : "r"(addr));
}
__device__ __forceinline__ void mma16816(float* d, const uint32_t* a,
                                         uint32_t b0, uint32_t b1) {
    asm volatile(
        "mma.sync.aligned.m16n8k16.row.col.f32.f16.f16.f32 "
        "{%0,%1,%2,%3}, {%4,%5,%6,%7}, {%8,%9}, {%0,%1,%2,%3};"
        : "+f"(d[0]), "+f"(d[1]), "+f"(d[2]), "+f"(d[3])
        : "r"(a[0]), "r"(a[1]), "r"(a[2]), "r"(a[3]), "r"(b0), "r"(b1));
}

// ---------------------------------------------------------------------------
// Kernel 0: conv2 weights -> fp16 LDSM-ready tiles, K permuted kk' = k*64+ci.
// grid (3, NE), 256 threads
// ---------------------------------------------------------------------------
__global__ void __launch_bounds__(256) k_prep(
    const float* __restrict__ wb3, const float* __restrict__ wb5,
    const float* __restrict__ wb7) {
    const int br = blockIdx.x, e = blockIdx.y;
    const float* wb = ((br == 0) ? wb3 : (br == 1) ? wb5 : wb7) + e * CH * 192;
    __half* dst = g_wb16 + (br * NE + e) * (CH * BSTR);
    for (int idx = threadIdx.x; idx < CH * BSTR; idx += 256) {
        const int c = idx / BSTR;
        const int kk = idx - c * BSTR;
        float v = 0.f;
        if (kk < 192) {
            const int k = kk >> 6;
            const int ci = kk & 63;
            v = wb[c * 192 + ci * 3 + k];
        }
        dst[idx] = __float2half_rn(v);
    }
}

// ---------------------------------------------------------------------------
// Kernel 1: STFT magnitudes (phasor recurrence)
// ---------------------------------------------------------------------------
__global__ void __launch_bounds__(128) k_stft(const float* __restrict__ x) {
    __shared__ float f[NFFT];
    const int fr = blockIdx.x, b = blockIdx.y, t = threadIdx.x;
    for (int i = t; i < NFFT; i += 128) {
        int m = fr * HOP + i - 128;
        if (m < 0) m = -m;
        else if (m >= NSAMP) m = 2 * NSAMP - 2 - m;
        const float win = 0.5f - 0.5f * cospif((float)i / 128.0f);
        f[i] = x[b * NSAMP + m] * win;
    }
    __syncthreads();
    float* magp = &g_mag[(b * NFRAMES + fr) * NBINS];
    if (t == 0) {
        float s0 = 0.f, s1 = 0.f;
#pragma unroll 8
        for (int n = 0; n < NFFT; n += 2) { s0 += f[n]; s1 += f[n + 1]; }
        magp[0] = fabsf(s0 + s1);
        magp[128] = fabsf(s0 - s1);
    } else {
        const float ang = (float)t / 128.0f;
        float c[4], s[4];
#pragma unroll
        for (int i = 0; i < 4; i++) { c[i] = cospif(ang * i); s[i] = sinpif(ang * i); }
        const float cD = cospif(ang * 4.0f), sD = sinpif(ang * 4.0f);
        float re_[4] = {0, 0, 0, 0}, im_[4] = {0, 0, 0, 0};
#pragma unroll 4
        for (int n4 = 0; n4 < 64; n4++) {
#pragma unroll
            for (int i = 0; i < 4; i++) {
                const float v = f[n4 * 4 + i];
                re_[i] += v * c[i]; im_[i] += v * s[i];
                const float cn = c[i] * cD - s[i] * sD;
                s[i] = c[i] * sD + s[i] * cD; c[i] = cn;
            }
        }
        const float re = (re_[0] + re_[1]) + (re_[2] + re_[3]);
        const float im = (im_[0] + im_[1]) + (im_[2] + im_[3]);
        magp[t] = sqrtf(re * re + im * im);
    }
}

// ---------------------------------------------------------------------------
// Kernel 2: pooling + gating MLP + top-2 + softmax
// ---------------------------------------------------------------------------
__global__ void __launch_bounds__(256) k_gate(
    const float* __restrict__ Wg1, const float* __restrict__ bg1,
    const float* __restrict__ Wg2, const float* __restrict__ bg2,
    const float* __restrict__ Wg3, const float* __restrict__ bg3) {
    __shared__ float p[NBINS]; __shared__ float h1[256];
    __shared__ float h2[128];  __shared__ float lg[NE];
    const int b = blockIdx.x, t = threadIdx.x;
    if (t < NBINS) {
        float s = 0.f;
        for (int fr = 0; fr < NFRAMES; fr++) s += g_mag[(b * NFRAMES + fr) * NBINS + t];
        p[t] = s * (1.0f / NFRAMES);
    }
    __syncthreads();
    { float s = bg1[t];
      for (int i = 0; i < NBINS; i++) s += p[i] * Wg1[i * 256 + t];
      h1[t] = fmaxf(s, 0.f); }
    __syncthreads();
    if (t < 128) {
        float s = bg2[t];
        for (int i = 0; i < 256; i++) s += h1[i] * Wg2[i * 128 + t];
        h2[t] = fmaxf(s, 0.f);
    }
    __syncthreads();
    if (t < NE) {
        float s = bg3[t];
        for (int i = 0; i < 128; i++) s += h2[i] * Wg3[i * NE + t];
        lg[t] = s;
    }
    __syncthreads();
    if (t == 0) {
        int i0 = 0; float v0 = lg[0];
        for (int j = 1; j < NE; j++) if (lg[j] > v0) { v0 = lg[j]; i0 = j; }
        int i1 = (i0 == 0) ? 1 : 0; float v1 = lg[i1];
        for (int j = 0; j < NE; j++) if (j != i0 && lg[j] > v1) { v1 = lg[j]; i1 = j; }
        const float e = expf(v1 - v0);
        const float inv = 1.f / (1.f + e);
        g_eidx[b * 2] = i0; g_eidx[b * 2 + 1] = i1;
        g_ew[b * 2] = inv;  g_ew[b * 2 + 1] = e * inv;
    }
}

// ---------------------------------------------------------------------------
// conv1 sliding-window loop (thread = fixed channel ch + p-range [pbeg,pend));
// per step: 2 broadcast xs LDS, ksz reg FMA, 1-2 contiguous .16 A-stores.
// A column layout kk' = k*64 + ch (K-permutation consistent with k_prep).
// ---------------------------------------------------------------------------
#define CONV1_LOOP(KSZ, PAD) do {                                             \
    float wr[KSZ];                                                            \
    _Pragma("unroll")                                                         \
    for (int k = 0; k < KSZ; k++) wr[k] = wgp[ch * KSZ + k];                  \
    const int idx0 = 2 * pbeg + 3 - (PAD);                                    \
    float win[KSZ + 2];                                                       \
    _Pragma("unroll")                                                         \
    for (int j = 0; j < KSZ; j++) win[j] = xs[idx0 + j];                      \
    _Pragma("unroll 3")                                                       \
    for (int p_i = pbeg; p_i < pend; p_i++) {                                 \
        float s = bias;                                                       \
        _Pragma("unroll")                                                     \
        for (int k = 0; k < KSZ; k++) s += wr[k] * win[k];                    \
        s = (2 * t0 - 1 + p_i >= 0) ? fmaxf(s, 0.f) : 0.f;                    \
        const __half hv = __float2half_rn(s);                                 \
        if ((p_i & 1) == 0) {                                                 \
            const int tt = p_i >> 1;                                          \
            if (tt < TOUT)                                                    \
                *(__half*)(smem + A_OFF + (uint32_t)(tt * ASTR + ch) * 2) = hv;        \
            if (tt >= 1)                                                      \
                *(__half*)(smem + A_OFF + (uint32_t)((tt - 1) * ASTR + 128 + ch) * 2) = hv; \
        } else {                                                              \
            *(__half*)(smem + A_OFF + (uint32_t)((p_i >> 1) * ASTR + 64 + ch) * 2) = hv;   \
        }                                                                     \
        _Pragma("unroll")                                                     \
        for (int k = 0; k < KSZ - 2; k++) win[k] = win[k + 2];                \
        win[KSZ - 2] = xs[idx0 + (p_i - pbeg) * 2 + KSZ];                     \
        win[KSZ - 1] = xs[idx0 + (p_i - pbeg) * 2 + KSZ + 1];                 \
    }                                                                         \
} while (0)

// ---------------------------------------------------------------------------
// Kernel 3: fused top-2 expert conv stack, fp16 HMMA, 4 CTAs/SM.
// ---------------------------------------------------------------------------
__global__ void __launch_bounds__(256, 4) k_expert(
    float* __restrict__ out, const float* __restrict__ x,
    const float* __restrict__ wa3, const float* __restrict__ ba3,
    const float* __restrict__ bb3,
    const float* __restrict__ wa5, const float* __restrict__ ba5,
    const float* __restrict__ bb5,
    const float* __restrict__ wa7, const float* __restrict__ ba7,
    const float* __restrict__ bb7) {
    extern __shared__ char smem[];
    const uint32_t sb = smem_u32(smem);
    float* xs = (float*)(smem + XS_OFF);

    const int tid  = threadIdx.x;
    const int wid  = tid >> 5;
    const int lane = tid & 31;
    const int tile = blockIdx.x, br = blockIdx.y, b = blockIdx.z;
    const int t0   = tile * TOUT;
    const int tg   = wid >> 1;
    const int ch0  = (wid & 1) * 32;

    const float* wap = (br == 0) ? wa3 : ((br == 1) ? wa5 : wa7);
    const float* bap = (br == 0) ? ba3 : ((br == 1) ? ba5 : ba7);
    const float* bbp = (br == 0) ? bb3 : ((br == 1) ? bb5 : bb7);
    const int ksz = 3 + 2 * br;

    const int   eidx[2] = { g_eidx[b * 2], g_eidx[b * 2 + 1] };
    const float ewgt[2] = { g_ew[b * 2],   g_ew[b * 2 + 1] };

    // stage x window: xi in [4*t0-5, 4*t0+266]
    const int xlo = 4 * t0 - 5;
    for (int i = tid; i < 272; i += 256) {
        const int xi = xlo + i;
        xs[i] = (xi >= 0 && xi < NSAMP) ? x[b * NSAMP + xi] : 0.f;
    }

    // conv1 thread mapping: fixed channel, quarter of p-range
    const int ch   = tid & 63;
    const int q    = tid >> 6;
    const int pbeg = q * 33;
    const int pend = (pbeg + 33 < 129) ? pbeg + 33 : 129;

    // ldmatrix lane offsets (bytes; + ks*32 added per k-step)
    const uint32_t aoff = (uint32_t)(((tg * 16 + (lane & 15)) * ASTR +
                                      ((lane & 16) ? 8 : 0)) * 2);
    const int brow = (lane & 7) + ((lane >> 1) & 8);
    const int bko  = (lane & 8) ? 8 : 0;
    const uint32_t boff0 = (uint32_t)(((ch0 + brow) * BSTR + bko) * 2);
    const uint32_t boff1 = (uint32_t)(((ch0 + 16 + brow) * BSTR + bko) * 2);

    float facc[16];
#pragma unroll
    for (int i = 0; i < 16; i++) facc[i] = 0.f;

    for (int ei = 0; ei < 2; ei++) {
        const int e = eidx[ei];
        const float wgt = ewgt[ei];
        __syncthreads();   // A/B free (prev GEMM done); xs ready on ei=0

        // stage fp16 B tile (pure 16B copy, 1600 uint4)
        {
            const uint4* src = (const uint4*)(g_wb16 + (br * NE + e) * (CH * BSTR));
            uint4* dst = (uint4*)(smem + B_OFF);
            for (int i = tid; i < (CH * BSTR * 2) / 16; i += 256) dst[i] = src[i];
        }

        // conv1 -> im2col A (weights/bias in registers, sliding x window)
        {
            const float* wgp = wap + e * CH * ksz;
            const float bias = bap[e * CH + ch];
            if (ksz == 3)      CONV1_LOOP(3, 1);
            else if (ksz == 5) CONV1_LOOP(5, 2);
            else               CONV1_LOOP(7, 3);
        }
        __syncthreads();

        // GEMM: 12 k-steps, 4 MMA each
        float acc[16];
#pragma unroll
        for (int i = 0; i < 16; i++) acc[i] = 0.f;

        for (int ks = 0; ks < 12; ks++) {
            const uint32_t kb = (uint32_t)(ks * 32);
            uint32_t a[4], b0[4], b1[4];
            ldsm_x4(a[0], a[1], a[2], a[3], sb + A_OFF + aoff + kb);
            ldsm_x4(b0[0], b0[1], b0[2], b0[3], sb + B_OFF + boff0 + kb);
            ldsm_x4(b1[0], b1[1], b1[2], b1[3], sb + B_OFF + boff1 + kb);
            mma16816(&acc[0],  a, b0[0], b0[1]);
            mma16816(&acc[4],  a, b0[2], b0[3]);
            mma16816(&acc[8],  a, b1[0], b1[1]);
            mma16816(&acc[12], a, b1[2], b1[3]);
        }

        // epilogue: bias + relu + gate-weighted accumulate (bias from L2)
        const float* bbe = bbp + e * CH;
#pragma unroll
        for (int nt = 0; nt < 4; nt++) {
            const int c0 = ch0 + nt * 8 + (lane & 3) * 2;
            const float b0 = bbe[c0], b1 = bbe[c0 + 1];
            facc[nt * 4 + 0] += wgt * fmaxf(acc[nt * 4 + 0] + b0, 0.f);
            facc[nt * 4 + 1] += wgt * fmaxf(acc[nt * 4 + 1] + b1, 0.f);
            facc[nt * 4 + 2] += wgt * fmaxf(acc[nt * 4 + 2] + b0, 0.f);
            facc[nt * 4 + 3] += wgt * fmaxf(acc[nt * 4 + 3] + b1, 0.f);
        }
    }

    // transpose via smem (reuse A region) then coalesced stores
    __syncthreads();
    float* stage = (float*)(smem + A_OFF) + wid * (32 * 17);
    {
        const int rt = lane >> 2;
#pragma unroll
        for (int nt = 0; nt < 4; nt++) {
            const int cl = nt * 8 + (lane & 3) * 2;   // local channel 0..31
            stage[(cl    ) * 17 + rt]     = facc[nt * 4 + 0];
            stage[(cl + 1) * 17 + rt]     = facc[nt * 4 + 1];
            stage[(cl    ) * 17 + rt + 8] = facc[nt * 4 + 2];
            stage[(cl + 1) * 17 + rt + 8] = facc[nt * 4 + 3];
        }
    }
    __syncwarp();
    {
        const int tl = lane & 15;
        const size_t obase = (size_t)(b * 192 + br * 64 + ch0) * L2LEN +
                             t0 + tg * 16 + tl;
#pragma unroll
        for (int it = 0; it < 16; it++) {
            const int cl = it * 2 + (lane >> 4);
            out[obase + (size_t)cl * L2LEN] = stage[cl * 17 + tl];
        }
    }
}

// ---------------------------------------------------------------------------
extern "C" void kernel_launch(void* const* d_in, const int* in_sizes, int n_in,
                              void* d_out, int out_size) {
    const float* x   = (const float*)d_in[0];
    const float* Wg1 = (const float*)d_in[1];
    const float* bg1 = (const float*)d_in[2];
    const float* Wg2 = (const float*)d_in[3];
    const float* bg2 = (const float*)d_in[4];
    const float* Wg3 = (const float*)d_in[5];
    const float* bg3 = (const float*)d_in[6];
    const float* wa3 = (const float*)d_in[7];
    const float* ba3 = (const float*)d_in[8];
    const float* wb3 = (const float*)d_in[9];
    const float* bb3 = (const float*)d_in[10];
    const float* wa5 = (const float*)d_in[11];
    const float* ba5 = (const float*)d_in[12];
    const float* wb5 = (const float*)d_in[13];
    const float* bb5 = (const float*)d_in[14];
    const float* wa7 = (const float*)d_in[15];
    const float* ba7 = (const float*)d_in[16];
    const float* wb7 = (const float*)d_in[17];
    const float* bb7 = (const float*)d_in[18];
    float* out = (float*)d_out;

    k_prep<<<dim3(3, NE), 256>>>(wb3, wb5, wb7);
    k_stft<<<dim3(NFRAMES, NB), 128>>>(x);
    k_gate<<<NB, 256>>>(Wg1, bg1, Wg2, bg2, Wg3, bg3);

    (void)cudaFuncSetAttribute(k_expert,
                               cudaFuncAttributeMaxDynamicSharedMemorySize,
                               SMEM_BYTES);
    k_expert<<<dim3(NTILES, 3, NB), 256, SMEM_BYTES>>>(
        out, x,
        wa3, ba3, bb3,
        wa5, ba5, bb5,
        wa7, ba7, bb7);
}

// round 13
// speedup vs baseline: 4.5749x; 1.1722x over previous
#include <cuda_runtime.h>
#include <cuda_fp16.h>
#include <math.h>
#include <stdint.h>

#define NSAMP 4096
#define NFFT 256
#define HOP 64
#define NFRAMES 65
#define NBINS 129
#define NB 64
#define NE 8
#define CH 64
#define L2LEN 1024
#define TOUT 64
#define NTILES (L2LEN / TOUT)

#define BSTR 200      // B fp16 row stride (400 B -> conflict-free LDSM)

// smem byte offsets (k_expert)
#define HT_OFF   0                     // hT: 129 rows x 128 B (swizzled)
#define B_OFF    16512                 // 64 x 200 fp16 = 25600
#define XWH_OFF  42112                 // XW hi: 128 x 12 tf32 = 6144
#define XWL_OFF  48256                 // XW lo: 6144
#define WATH_OFF 54400                 // WAt hi: 8 x 72 tf32 = 2304
#define WATL_OFF 56704                 // WAt lo: 2304
#define XS_OFF   59008                 // 272 floats = 1088
#define BAS_OFF  60096                 // 64 floats
#define SMEM_BYTES 60352               // -> 3 CTAs/SM

// scratch
__device__ float g_mag[NB * NFRAMES * NBINS];
__device__ int   g_eidx[NB * 2];
__device__ float g_ew[NB * 2];
__device__ __align__(16) __half g_wb16[3 * NE * CH * BSTR];

__device__ __forceinline__ uint32_t smem_u32(const void* p) {
    uint32_t a;
    asm("{ .reg .u64 t; cvta.to.shared.u64 t, %1; cvt.u32.u64 %0, t; }"
        : "=r"(a) : "l"(p));
    return a;
}
__device__ __forceinline__ void ldsm_x4(uint32_t& r0, uint32_t& r1,
                                        uint32_t& r2, uint32_t& r3,
                                        uint32_t addr) {
    asm volatile("ldmatrix.sync.aligned.m8n8.x4.shared.b16 {%0,%1,%2,%3}, [%4];"
                 : "=r"(r0), "=r"(r1), "=r"(r2), "=r"(r3) : "r"(addr));
}
__device__ __forceinline__ void mma16816(float* d, const uint32_t* a,
                                         uint32_t b0, uint32_t b1) {
    asm volatile(
        "mma.sync.aligned.m16n8k16.row.col.f32.f16.f16.f32 "
        "{%0,%1,%2,%3}, {%4,%5,%6,%7}, {%8,%9}, {%0,%1,%2,%3};"
        : "+f"(d[0]), "+f"(d[1]), "+f"(d[2]), "+f"(d[3])
        : "r"(a[0]), "r"(a[1]), "r"(a[2]), "r"(a[3]), "r"(b0), "r"(b1));
}
__device__ __forceinline__ void mma1688tf32(float* d, const uint32_t* a,
                                            uint32_t b0, uint32_t b1) {
    asm volatile(
        "mma.sync.aligned.m16n8k8.row.col.f32.tf32.tf32.f32 "
        "{%0,%1,%2,%3}, {%4,%5,%6,%7}, {%8,%9}, {%0,%1,%2,%3};"
        : "+f"(d[0]), "+f"(d[1]), "+f"(d[2]), "+f"(d[3])
        : "r"(a[0]), "r"(a[1]), "r"(a[2]), "r"(a[3]), "r"(b0), "r"(b1));
}
__device__ __forceinline__ uint32_t f2tf32(float v) {
    uint32_t u;
    asm("cvt.rna.tf32.f32 %0, %1;" : "=r"(u) : "f"(v));
    return u;
}

// ---------------------------------------------------------------------------
// Kernel 0: conv2 weights -> fp16 LDSM-ready tiles, kk' = k*64 + ci
// ---------------------------------------------------------------------------
__global__ void __launch_bounds__(256) k_prep(
    const float* __restrict__ wb3, const float* __restrict__ wb5,
    const float* __restrict__ wb7) {
    const int br = blockIdx.x, e = blockIdx.y;
    const float* wb = ((br == 0) ? wb3 : (br == 1) ? wb5 : wb7) + e * CH * 192;
    __half* dst = g_wb16 + (br * NE + e) * (CH * BSTR);
    for (int idx = threadIdx.x; idx < CH * BSTR; idx += 256) {
        const int c = idx / BSTR;
        const int kk = idx - c * BSTR;
        float v = 0.f;
        if (kk < 192) v = wb[c * 192 + (kk & 63) * 3 + (kk >> 6)];
        dst[idx] = __float2half_rn(v);
    }
}

// ---------------------------------------------------------------------------
// Kernel 1: STFT magnitudes, symmetry-folded phasor DFT (half the FMAs)
// ---------------------------------------------------------------------------
__global__ void __launch_bounds__(128) k_stft(const float* __restrict__ x) {
    __shared__ float f[NFFT];
    __shared__ float fe[129], fo[129];
    const int fr = blockIdx.x, b = blockIdx.y, t = threadIdx.x;
    for (int i = t; i < NFFT; i += 128) {
        int m = fr * HOP + i - 128;
        if (m < 0) m = -m;
        else if (m >= NSAMP) m = 2 * NSAMP - 2 - m;
        const float win = 0.5f - 0.5f * cospif((float)i / 128.0f);
        f[i] = x[b * NSAMP + m] * win;
    }
    __syncthreads();
    if (t == 0) { fe[128] = 0.f; fo[128] = 0.f; }
    else        { fe[t] = f[t] + f[256 - t]; fo[t] = f[t] - f[256 - t]; }
    __syncthreads();

    float* magp = &g_mag[(b * NFRAMES + fr) * NBINS];
    if (t == 0) {
        float s0 = 0.f, s1 = 0.f;
#pragma unroll 8
        for (int n = 0; n < NFFT; n += 2) { s0 += f[n]; s1 += f[n + 1]; }
        magp[0] = fabsf(s0 + s1);
        magp[128] = fabsf(s0 - s1);
    } else {
        const float ang = (float)t / 128.0f;
        float c[4], s[4];
#pragma unroll
        for (int i = 0; i < 4; i++) {
            c[i] = cospif(ang * (float)(1 + i));
            s[i] = sinpif(ang * (float)(1 + i));
        }
        const float cD = cospif(ang * 4.0f), sD = sinpif(ang * 4.0f);
        float re = f[0] + ((t & 1) ? -f[128] : f[128]);
        float im = 0.f;
#pragma unroll 4
        for (int j = 0; j < 32; j++) {
            const int nb = 4 * j + 1;
#pragma unroll
            for (int i = 0; i < 4; i++) {
                re += fe[nb + i] * c[i];
                im += fo[nb + i] * s[i];
                const float cn = c[i] * cD - s[i] * sD;
                s[i] = c[i] * sD + s[i] * cD; c[i] = cn;
            }
        }
        magp[t] = sqrtf(re * re + im * im);
    }
}

// ---------------------------------------------------------------------------
// Kernel 2: pooling + gating MLP + top-2 + softmax
// ---------------------------------------------------------------------------
__global__ void __launch_bounds__(256) k_gate(
    const float* __restrict__ Wg1, const float* __restrict__ bg1,
    const float* __restrict__ Wg2, const float* __restrict__ bg2,
    const float* __restrict__ Wg3, const float* __restrict__ bg3) {
    __shared__ float p[NBINS]; __shared__ float h1[256];
    __shared__ float h2[128];  __shared__ float lg[NE];
    const int b = blockIdx.x, t = threadIdx.x;
    if (t < NBINS) {
        float s = 0.f;
        for (int fr = 0; fr < NFRAMES; fr++) s += g_mag[(b * NFRAMES + fr) * NBINS + t];
        p[t] = s * (1.0f / NFRAMES);
    }
    __syncthreads();
    { float s = bg1[t];
      for (int i = 0; i < NBINS; i++) s += p[i] * Wg1[i * 256 + t];
      h1[t] = fmaxf(s, 0.f); }
    __syncthreads();
    if (t < 128) {
        float s = bg2[t];
        for (int i = 0; i < 256; i++) s += h1[i] * Wg2[i * 128 + t];
        h2[t] = fmaxf(s, 0.f);
    }
    __syncthreads();
    if (t < NE) {
        float s = bg3[t];
        for (int i = 0; i < 128; i++) s += h2[i] * Wg3[i * NE + t];
        lg[t] = s;
    }
    __syncthreads();
    if (t == 0) {
        int i0 = 0; float v0 = lg[0];
        for (int j = 1; j < NE; j++) if (lg[j] > v0) { v0 = lg[j]; i0 = j; }
        int i1 = (i0 == 0) ? 1 : 0; float v1 = lg[i1];
        for (int j = 0; j < NE; j++) if (j != i0 && lg[j] > v1) { v1 = lg[j]; i1 = j; }
        const float e = expf(v1 - v0);
        const float inv = 1.f / (1.f + e);
        g_eidx[b * 2] = i0; g_eidx[b * 2 + 1] = i1;
        g_ew[b * 2] = inv;  g_ew[b * 2 + 1] = e * inv;
    }
}

// ---------------------------------------------------------------------------
// Kernel 3: fused top-2 expert stack. conv1 via tf32 MMA (3-pass hi/lo),
// conv2 via fp16 HMMA with 3 k-shifted A reads from swizzled hT.
// grid (16, 3, NB), 256 threads, 60.4KB smem -> 3 CTAs/SM.
// ---------------------------------------------------------------------------
__global__ void __launch_bounds__(256, 3) k_expert(
    float* __restrict__ out, const float* __restrict__ x,
    const float* __restrict__ wa3, const float* __restrict__ ba3,
    const float* __restrict__ bb3,
    const float* __restrict__ wa5, const float* __restrict__ ba5,
    const float* __restrict__ bb5,
    const float* __restrict__ wa7, const float* __restrict__ ba7,
    const float* __restrict__ bb7) {
    extern __shared__ char smem[];
    const uint32_t sb = smem_u32(smem);
    float* xs  = (float*)(smem + XS_OFF);
    float* bas = (float*)(smem + BAS_OFF);

    const int tid  = threadIdx.x;
    const int wid  = tid >> 5;
    const int lane = tid & 31;
    const int tile = blockIdx.x, br = blockIdx.y, b = blockIdx.z;
    const int t0   = tile * TOUT;
    const int tg   = wid >> 1;
    const int ch0  = (wid & 1) * 32;
    const int ksz  = 3 + 2 * br;
    const int pad  = ksz >> 1;

    const float* wap = (br == 0) ? wa3 : ((br == 1) ? wa5 : wa7);
    const float* bap = (br == 0) ? ba3 : ((br == 1) ? ba5 : ba7);
    const float* bbp = (br == 0) ? bb3 : ((br == 1) ? bb5 : bb7);

    const int   eidx[2] = { g_eidx[b * 2], g_eidx[b * 2 + 1] };
    const float ewgt[2] = { g_ew[b * 2],   g_ew[b * 2 + 1] };

    // stage x window: xi in [4*t0-5, 4*t0+266]
    const int xlo = 4 * t0 - 5;
    for (int i = tid; i < 272; i += 256) {
        const int xi = xlo + i;
        xs[i] = (xi >= 0 && xi < NSAMP) ? x[b * NSAMP + xi] : 0.f;
    }
    __syncthreads();

    // build XW (im2col of x) once: XW[p][k] = xs[2p + 3 - pad + k], tf32 hi/lo
    {
        uint32_t* xwh = (uint32_t*)(smem + XWH_OFF);
        uint32_t* xwl = (uint32_t*)(smem + XWL_OFF);
        for (int idx = tid; idx < 128 * 8; idx += 256) {
            const int p = idx >> 3, k = idx & 7;
            const float v = xs[2 * p + 3 - pad + k];
            const uint32_t uhi = f2tf32(v);
            const float vlo = v - __uint_as_float(uhi);
            xwh[p * 12 + k] = uhi;
            xwl[p * 12 + k] = f2tf32(vlo);
        }
    }

    // conv1 MMA fragment lane constants
    const int r4 = lane >> 2, c4 = lane & 3;
    // conv2 ldmatrix lane constants
    const int trow = tg * 16 + (lane & 15);
    const uint32_t hb = (lane & 16) ? 1u : 0u;
    const int brow = (lane & 7) + ((lane >> 1) & 8);
    const int bko  = (lane & 8) ? 8 : 0;
    const uint32_t boff0 = (uint32_t)(((ch0 + brow) * BSTR + bko) * 2);
    const uint32_t boff1 = (uint32_t)(((ch0 + 16 + brow) * BSTR + bko) * 2);

    float facc[16];
#pragma unroll
    for (int i = 0; i < 16; i++) facc[i] = 0.f;

    for (int ei = 0; ei < 2; ei++) {
        const int e = eidx[ei];
        const float wgt = ewgt[ei];
        __syncthreads();   // tiles free (prev GEMM done); XW built (ei=0)

        // stage B fp16 tile + WAt tf32 hi/lo + conv1 bias
        {
            const uint4* src = (const uint4*)(g_wb16 + (br * NE + e) * (CH * BSTR));
            uint4* dst = (uint4*)(smem + B_OFF);
            for (int i = tid; i < (CH * BSTR * 2) / 16; i += 256) dst[i] = src[i];
        }
        {
            uint32_t* wth = (uint32_t*)(smem + WATH_OFF);
            uint32_t* wtl = (uint32_t*)(smem + WATL_OFF);
            for (int idx = tid; idx < 8 * 64; idx += 256) {
                const int k = idx >> 6, ch = idx & 63;
                const float v = (k < ksz) ? wap[e * CH * ksz + ch * ksz + k] : 0.f;
                const uint32_t uhi = f2tf32(v);
                const float vlo = v - __uint_as_float(uhi);
                wth[k * 72 + ch] = uhi;
                wtl[k * 72 + ch] = f2tf32(vlo);
            }
            if (tid < CH) bas[tid] = bap[e * CH + tid];
        }
        __syncthreads();

        // conv1 via tf32 MMA: D[pos16, ch64] per warp; 3 passes hi/lo
        {
            const uint32_t* xwh = (const uint32_t*)(smem + XWH_OFF);
            const uint32_t* xwl = (const uint32_t*)(smem + XWL_OFF);
            const uint32_t* wth = (const uint32_t*)(smem + WATH_OFF);
            const uint32_t* wtl = (const uint32_t*)(smem + WATL_OFF);
            const int pos0 = wid * 16;
            uint32_t ahi[4], alo[4];
            ahi[0] = xwh[(pos0 + r4) * 12 + c4];
            ahi[1] = xwh[(pos0 + r4 + 8) * 12 + c4];
            ahi[2] = xwh[(pos0 + r4) * 12 + c4 + 4];
            ahi[3] = xwh[(pos0 + r4 + 8) * 12 + c4 + 4];
            alo[0] = xwl[(pos0 + r4) * 12 + c4];
            alo[1] = xwl[(pos0 + r4 + 8) * 12 + c4];
            alo[2] = xwl[(pos0 + r4) * 12 + c4 + 4];
            alo[3] = xwl[(pos0 + r4 + 8) * 12 + c4 + 4];
            const int rr0 = pos0 + r4;
            const int rr1 = rr0 + 8;
            const bool zr = (t0 == 0) && (rr0 == 0);
#pragma unroll
            for (int nt = 0; nt < 8; nt++) {
                const uint32_t bh0 = wth[c4 * 72 + nt * 8 + r4];
                const uint32_t bh1 = wth[(c4 + 4) * 72 + nt * 8 + r4];
                const uint32_t bl0 = wtl[c4 * 72 + nt * 8 + r4];
                const uint32_t bl1 = wtl[(c4 + 4) * 72 + nt * 8 + r4];
                float dd[4] = {0.f, 0.f, 0.f, 0.f};
                mma1688tf32(dd, ahi, bh0, bh1);
                mma1688tf32(dd, alo, bh0, bh1);
                mma1688tf32(dd, ahi, bl0, bl1);
                const int c0 = nt * 8 + 2 * c4;
                const float ba0 = bas[c0], ba1 = bas[c0 + 1];
                float h00 = fmaxf(dd[0] + ba0, 0.f);
                float h01 = fmaxf(dd[1] + ba1, 0.f);
                const float h10 = fmaxf(dd[2] + ba0, 0.f);
                const float h11 = fmaxf(dd[3] + ba1, 0.f);
                if (zr) { h00 = 0.f; h01 = 0.f; }
                *(__half2*)(smem + HT_OFF + rr0 * 128 +
                            ((nt ^ ((rr0 >> 1) & 7)) * 16) + c4 * 4) =
                    __floats2half2_rn(h00, h01);
                *(__half2*)(smem + HT_OFF + rr1 * 128 +
                            ((nt ^ ((rr1 >> 1) & 7)) * 16) + c4 * 4) =
                    __floats2half2_rn(h10, h11);
            }
        }
        // position 128 (needed by k=2 at t=63): scalar
        if (tid < CH) {
            const int ch = tid;
            float s = bas[ch];
            const float* wr = wap + e * CH * ksz + ch * ksz;
            const int idx0 = 259 - pad;
            for (int k = 0; k < ksz; k++) s += wr[k] * xs[idx0 + k];
            s = fmaxf(s, 0.f);
            *(__half*)(smem + HT_OFF + 128 * 128 + (ch >> 3) * 16 + (ch & 7) * 2) =
                __float2half_rn(s);
        }
        __syncthreads();

        // conv2 GEMM: 3 k-shifts x 4 ci-steps, fp16 HMMA
        float acc[16];
#pragma unroll
        for (int i = 0; i < 16; i++) acc[i] = 0.f;

#pragma unroll
        for (int k = 0; k < 3; k++) {
            const int r = 2 * trow + k;
            const uint32_t abase = sb + HT_OFF + (uint32_t)r * 128;
            const uint32_t m = (uint32_t)(r >> 1) & 7u;
#pragma unroll
            for (int ks2 = 0; ks2 < 4; ks2++) {
                const uint32_t aaddr = abase + ((((uint32_t)ks2 * 2 + hb) ^ m) * 16);
                const uint32_t kb = (uint32_t)((k * 4 + ks2) * 32);
                uint32_t a[4], b0[4], b1[4];
                ldsm_x4(a[0], a[1], a[2], a[3], aaddr);
                ldsm_x4(b0[0], b0[1], b0[2], b0[3], sb + B_OFF + boff0 + kb);
                ldsm_x4(b1[0], b1[1], b1[2], b1[3], sb + B_OFF + boff1 + kb);
                mma16816(&acc[0],  a, b0[0], b0[1]);
                mma16816(&acc[4],  a, b0[2], b0[3]);
                mma16816(&acc[8],  a, b1[0], b1[1]);
                mma16816(&acc[12], a, b1[2], b1[3]);
            }
        }

        // epilogue: bias + relu + gate-weighted accumulate
        const float* bbe = bbp + e * CH;
#pragma unroll
        for (int nt = 0; nt < 4; nt++) {
            const int c0 = ch0 + nt * 8 + (lane & 3) * 2;
            const float b0 = bbe[c0], b1 = bbe[c0 + 1];
            facc[nt * 4 + 0] += wgt * fmaxf(acc[nt * 4 + 0] + b0, 0.f);
            facc[nt * 4 + 1] += wgt * fmaxf(acc[nt * 4 + 1] + b1, 0.f);
            facc[nt * 4 + 2] += wgt * fmaxf(acc[nt * 4 + 2] + b0, 0.f);
            facc[nt * 4 + 3] += wgt * fmaxf(acc[nt * 4 + 3] + b1, 0.f);
        }
    }

    // transpose via smem (reuse hT/B region) then coalesced stores
    __syncthreads();
    float* stage = (float*)(smem + HT_OFF) + wid * (32 * 17);
    {
        const int rt = lane >> 2;
#pragma unroll
        for (int nt = 0; nt < 4; nt++) {
            const int cl = nt * 8 + (lane & 3) * 2;
            stage[(cl    ) * 17 + rt]     = facc[nt * 4 + 0];
            stage[(cl + 1) * 17 + rt]     = facc[nt * 4 + 1];
            stage[(cl    ) * 17 + rt + 8] = facc[nt * 4 + 2];
            stage[(cl + 1) * 17 + rt + 8] = facc[nt * 4 + 3];
        }
    }
    __syncwarp();
    {
        const int tl = lane & 15;
        const size_t obase = (size_t)(b * 192 + br * 64 + ch0) * L2LEN +
                             t0 + tg * 16 + tl;
#pragma unroll
        for (int it = 0; it < 16; it++) {
            const int cl = it * 2 + (lane >> 4);
            out[obase + (size_t)cl * L2LEN] = stage[cl * 17 + tl];
        }
    }
}

// ---------------------------------------------------------------------------
extern "C" void kernel_launch(void* const* d_in, const int* in_sizes, int n_in,
                              void* d_out, int out_size) {
    const float* x   = (const float*)d_in[0];
    const float* Wg1 = (const float*)d_in[1];
    const float* bg1 = (const float*)d_in[2];
    const float* Wg2 = (const float*)d_in[3];
    const float* bg2 = (const float*)d_in[4];
    const float* Wg3 = (const float*)d_in[5];
    const float* bg3 = (const float*)d_in[6];
    const float* wa3 = (const float*)d_in[7];
    const float* ba3 = (const float*)d_in[8];
    const float* wb3 = (const float*)d_in[9];
    const float* bb3 = (const float*)d_in[10];
    const float* wa5 = (const float*)d_in[11];
    const float* ba5 = (const float*)d_in[12];
    const float* wb5 = (const float*)d_in[13];
    const float* bb5 = (const float*)d_in[14];
    const float* wa7 = (const float*)d_in[15];
    const float* ba7 = (const float*)d_in[16];
    const float* wb7 = (const float*)d_in[17];
    const float* bb7 = (const float*)d_in[18];
    float* out = (float*)d_out;

    k_prep<<<dim3(3, NE), 256>>>(wb3, wb5, wb7);
    k_stft<<<dim3(NFRAMES, NB), 128>>>(x);
    k_gate<<<NB, 256>>>(Wg1, bg1, Wg2, bg2, Wg3, bg3);

    (void)cudaFuncSetAttribute(k_expert,
                               cudaFuncAttributeMaxDynamicSharedMemorySize,
                               SMEM_BYTES);
    k_expert<<<dim3(NTILES, 3, NB), 256, SMEM_BYTES>>>(
        out, x,
        wa3, ba3, bb3,
        wa5, ba5, bb5,
        wa7, ba7, bb7);
}

// round 14
// speedup vs baseline: 4.8277x; 1.0553x over previous
#include <cuda_runtime.h>
#include <cuda_fp16.h>
#include <math.h>
#include <stdint.h>

#define NSAMP 4096
#define NFFT 256
#define HOP 64
#define NFRAMES 65
#define NBINS 129
#define NB 64
#define NE 8
#define CH 64
#define L2LEN 1024
#define TOUT 64
#define NTILES (L2LEN / TOUT)

#define BSTR 200      // B fp16 row stride (400 B -> conflict-free LDSM)

// smem byte offsets (k_expert)
#define HT_OFF   0                     // hT: 129 rows x 128 B (swizzled)
#define B_OFF    16512                 // 64 x 200 fp16 = 25600
#define WATH_OFF 42112                 // WAt hi: 8 x 72 tf32 = 2304
#define WATL_OFF 44416                 // WAt lo: 2304
#define XS_OFF   46720                 // 272 floats = 1088
#define BAS_OFF  47808                 // 64 floats
#define SMEM_BYTES 48064               // -> 4 CTAs/SM (192.3 KB)

// scratch
__device__ float g_mag[NB * NFRAMES * NBINS];
__device__ int   g_eidx[NB * 2];
__device__ float g_ew[NB * 2];
__device__ __align__(16) __half g_wb16[3 * NE * CH * BSTR];

__device__ __forceinline__ uint32_t smem_u32(const void* p) {
    uint32_t a;
    asm("{ .reg .u64 t; cvta.to.shared.u64 t, %1; cvt.u32.u64 %0, t; }"
        : "=r"(a) : "l"(p));
    return a;
}
__device__ __forceinline__ void ldsm_x4(uint32_t& r0, uint32_t& r1,
                                        uint32_t& r2, uint32_t& r3,
                                        uint32_t addr) {
    asm volatile("ldmatrix.sync.aligned.m8n8.x4.shared.b16 {%0,%1,%2,%3}, [%4];"
                 : "=r"(r0), "=r"(r1), "=r"(r2), "=r"(r3) : "r"(addr));
}
__device__ __forceinline__ void mma16816(float* d, const uint32_t* a,
                                         uint32_t b0, uint32_t b1) {
    asm volatile(
        "mma.sync.aligned.m16n8k16.row.col.f32.f16.f16.f32 "
        "{%0,%1,%2,%3}, {%4,%5,%6,%7}, {%8,%9}, {%0,%1,%2,%3};"
        : "+f"(d[0]), "+f"(d[1]), "+f"(d[2]), "+f"(d[3])
        : "r"(a[0]), "r"(a[1]), "r"(a[2]), "r"(a[3]), "r"(b0), "r"(b1));
}
__device__ __forceinline__ void mma1688tf32(float* d, const uint32_t* a,
                                            uint32_t b0, uint32_t b1) {
    asm volatile(
        "mma.sync.aligned.m16n8k8.row.col.f32.tf32.tf32.f32 "
        "{%0,%1,%2,%3}, {%4,%5,%6,%7}, {%8,%9}, {%0,%1,%2,%3};"
        : "+f"(d[0]), "+f"(d[1]), "+f"(d[2]), "+f"(d[3])
        : "r"(a[0]), "r"(a[1]), "r"(a[2]), "r"(a[3]), "r"(b0), "r"(b1));
}
__device__ __forceinline__ uint32_t f2tf32(float v) {
    uint32_t u;
    asm("cvt.rna.tf32.f32 %0, %1;" : "=r"(u) : "f"(v));
    return u;
}

// ---------------------------------------------------------------------------
// Kernel 0: conv2 weights -> fp16 LDSM-ready tiles, kk' = k*64 + ci
// ---------------------------------------------------------------------------
__global__ void __launch_bounds__(256) k_prep(
    const float* __restrict__ wb3, const float* __restrict__ wb5,
    const float* __restrict__ wb7) {
    const int br = blockIdx.x, e = blockIdx.y;
    const float* wb = ((br == 0) ? wb3 : (br == 1) ? wb5 : wb7) + e * CH * 192;
    __half* dst = g_wb16 + (br * NE + e) * (CH * BSTR);
    for (int idx = threadIdx.x; idx < CH * BSTR; idx += 256) {
        const int c = idx / BSTR;
        const int kk = idx - c * BSTR;
        float v = 0.f;
        if (kk < 192) v = wb[c * 192 + (kk & 63) * 3 + (kk >> 6)];
        dst[idx] = __float2half_rn(v);
    }
}

// ---------------------------------------------------------------------------
// Kernel 1: STFT magnitudes, symmetry-folded phasor DFT
// ---------------------------------------------------------------------------
__global__ void __launch_bounds__(128) k_stft(const float* __restrict__ x) {
    __shared__ float f[NFFT];
    __shared__ float fe[129], fo[129];
    const int fr = blockIdx.x, b = blockIdx.y, t = threadIdx.x;
    for (int i = t; i < NFFT; i += 128) {
        int m = fr * HOP + i - 128;
        if (m < 0) m = -m;
        else if (m >= NSAMP) m = 2 * NSAMP - 2 - m;
        const float win = 0.5f - 0.5f * cospif((float)i / 128.0f);
        f[i] = x[b * NSAMP + m] * win;
    }
    __syncthreads();
    if (t == 0) { fe[128] = 0.f; fo[128] = 0.f; }
    else        { fe[t] = f[t] + f[256 - t]; fo[t] = f[t] - f[256 - t]; }
    __syncthreads();

    float* magp = &g_mag[(b * NFRAMES + fr) * NBINS];
    if (t == 0) {
        float s0 = 0.f, s1 = 0.f;
#pragma unroll 8
        for (int n = 0; n < NFFT; n += 2) { s0 += f[n]; s1 += f[n + 1]; }
        magp[0] = fabsf(s0 + s1);
        magp[128] = fabsf(s0 - s1);
    } else {
        const float ang = (float)t / 128.0f;
        float c[4], s[4];
#pragma unroll
        for (int i = 0; i < 4; i++) {
            c[i] = cospif(ang * (float)(1 + i));
            s[i] = sinpif(ang * (float)(1 + i));
        }
        const float cD = cospif(ang * 4.0f), sD = sinpif(ang * 4.0f);
        float re = f[0] + ((t & 1) ? -f[128] : f[128]);
        float im = 0.f;
#pragma unroll 4
        for (int j = 0; j < 32; j++) {
            const int nb = 4 * j + 1;
#pragma unroll
            for (int i = 0; i < 4; i++) {
                re += fe[nb + i] * c[i];
                im += fo[nb + i] * s[i];
                const float cn = c[i] * cD - s[i] * sD;
                s[i] = c[i] * sD + s[i] * cD; c[i] = cn;
            }
        }
        magp[t] = sqrtf(re * re + im * im);
    }
}

// ---------------------------------------------------------------------------
// Kernel 2: pooling + gating MLP + top-2 + softmax
// ---------------------------------------------------------------------------
__global__ void __launch_bounds__(256) k_gate(
    const float* __restrict__ Wg1, const float* __restrict__ bg1,
    const float* __restrict__ Wg2, const float* __restrict__ bg2,
    const float* __restrict__ Wg3, const float* __restrict__ bg3) {
    __shared__ float p[NBINS]; __shared__ float h1[256];
    __shared__ float h2[128];  __shared__ float lg[NE];
    const int b = blockIdx.x, t = threadIdx.x;
    if (t < NBINS) {
        float s = 0.f;
        for (int fr = 0; fr < NFRAMES; fr++) s += g_mag[(b * NFRAMES + fr) * NBINS + t];
        p[t] = s * (1.0f / NFRAMES);
    }
    __syncthreads();
    { float s = bg1[t];
      for (int i = 0; i < NBINS; i++) s += p[i] * Wg1[i * 256 + t];
      h1[t] = fmaxf(s, 0.f); }
    __syncthreads();
    if (t < 128) {
        float s = bg2[t];
        for (int i = 0; i < 256; i++) s += h1[i] * Wg2[i * 128 + t];
        h2[t] = fmaxf(s, 0.f);
    }
    __syncthreads();
    if (t < NE) {
        float s = bg3[t];
        for (int i = 0; i < 128; i++) s += h2[i] * Wg3[i * NE + t];
        lg[t] = s;
    }
    __syncthreads();
    if (t == 0) {
        int i0 = 0; float v0 = lg[0];
        for (int j = 1; j < NE; j++) if (lg[j] > v0) { v0 = lg[j]; i0 = j; }
        int i1 = (i0 == 0) ? 1 : 0; float v1 = lg[i1];
        for (int j = 0; j < NE; j++) if (j != i0 && lg[j] > v1) { v1 = lg[j]; i1 = j; }
        const float e = expf(v1 - v0);
        const float inv = 1.f / (1.f + e);
        g_eidx[b * 2] = i0; g_eidx[b * 2 + 1] = i1;
        g_ew[b * 2] = inv;  g_ew[b * 2 + 1] = e * inv;
    }
}

// ---------------------------------------------------------------------------
// Kernel 3: fused top-2 expert stack. conv1 via tf32 MMA (A frags straight
// from xs, hi/lo split in regs), conv2 via fp16 HMMA from swizzled hT.
// grid (16, 3, NB), 256 threads, 48.1KB smem -> 4 CTAs/SM.
// ---------------------------------------------------------------------------
__global__ void __launch_bounds__(256, 4) k_expert(
    float* __restrict__ out, const float* __restrict__ x,
    const float* __restrict__ wa3, const float* __restrict__ ba3,
    const float* __restrict__ bb3,
    const float* __restrict__ wa5, const float* __restrict__ ba5,
    const float* __restrict__ bb5,
    const float* __restrict__ wa7, const float* __restrict__ ba7,
    const float* __restrict__ bb7) {
    extern __shared__ char smem[];
    const uint32_t sb = smem_u32(smem);
    float* xs  = (float*)(smem + XS_OFF);
    float* bas = (float*)(smem + BAS_OFF);

    const int tid  = threadIdx.x;
    const int wid  = tid >> 5;
    const int lane = tid & 31;
    const int tile = blockIdx.x, br = blockIdx.y, b = blockIdx.z;
    const int t0   = tile * TOUT;
    const int tg   = wid >> 1;
    const int ch0  = (wid & 1) * 32;
    const int ksz  = 3 + 2 * br;
    const int pad  = ksz >> 1;

    const float* wap = (br == 0) ? wa3 : ((br == 1) ? wa5 : wa7);
    const float* bap = (br == 0) ? ba3 : ((br == 1) ? ba5 : ba7);
    const float* bbp = (br == 0) ? bb3 : ((br == 1) ? bb5 : bb7);

    const int   eidx[2] = { g_eidx[b * 2], g_eidx[b * 2 + 1] };
    const float ewgt[2] = { g_ew[b * 2],   g_ew[b * 2 + 1] };

    // stage x window: xi in [4*t0-5, 4*t0+266]
    const int xlo = 4 * t0 - 5;
    for (int i = tid; i < 272; i += 256) {
        const int xi = xlo + i;
        xs[i] = (xi >= 0 && xi < NSAMP) ? x[b * NSAMP + xi] : 0.f;
    }

    // conv1 MMA fragment lane constants
    const int r4 = lane >> 2, c4 = lane & 3;
    // conv2 ldmatrix lane constants
    const int trow = tg * 16 + (lane & 15);
    const uint32_t hb = (lane & 16) ? 1u : 0u;
    const int brow = (lane & 7) + ((lane >> 1) & 8);
    const int bko  = (lane & 8) ? 8 : 0;
    const uint32_t boff0 = (uint32_t)(((ch0 + brow) * BSTR + bko) * 2);
    const uint32_t boff1 = (uint32_t)(((ch0 + 16 + brow) * BSTR + bko) * 2);

    float facc[16];
#pragma unroll
    for (int i = 0; i < 16; i++) facc[i] = 0.f;

    for (int ei = 0; ei < 2; ei++) {
        const int e = eidx[ei];
        const float wgt = ewgt[ei];
        __syncthreads();   // tiles free (prev GEMM done); xs ready (ei=0)

        // stage B fp16 tile + WAt tf32 hi/lo + conv1 bias
        {
            const uint4* src = (const uint4*)(g_wb16 + (br * NE + e) * (CH * BSTR));
            uint4* dst = (uint4*)(smem + B_OFF);
            for (int i = tid; i < (CH * BSTR * 2) / 16; i += 256) dst[i] = src[i];
        }
        {
            uint32_t* wth = (uint32_t*)(smem + WATH_OFF);
            uint32_t* wtl = (uint32_t*)(smem + WATL_OFF);
            for (int idx = tid; idx < 8 * 64; idx += 256) {
                const int k = idx >> 6, ch = idx & 63;
                const float v = (k < ksz) ? wap[e * CH * ksz + ch * ksz + k] : 0.f;
                const uint32_t uhi = f2tf32(v);
                const float vlo = v - __uint_as_float(uhi);
                wth[k * 72 + ch] = uhi;
                wtl[k * 72 + ch] = f2tf32(vlo);
            }
            if (tid < CH) bas[tid] = bap[e * CH + tid];
        }
        __syncthreads();

        // conv1 via tf32 MMA: D[pos16, ch64] per warp; A frags direct from xs
        {
            const uint32_t* wth = (const uint32_t*)(smem + WATH_OFF);
            const uint32_t* wtl = (const uint32_t*)(smem + WATL_OFF);
            const int pos0 = wid * 16;
            const int base0 = 2 * (pos0 + r4) + 3 - pad;
            const float xv0 = xs[base0 + c4];
            const float xv1 = xs[base0 + 16 + c4];
            const float xv2 = xs[base0 + c4 + 4];
            const float xv3 = xs[base0 + 16 + c4 + 4];
            uint32_t ahi[4], alo[4];
            ahi[0] = f2tf32(xv0); alo[0] = f2tf32(xv0 - __uint_as_float(ahi[0]));
            ahi[1] = f2tf32(xv1); alo[1] = f2tf32(xv1 - __uint_as_float(ahi[1]));
            ahi[2] = f2tf32(xv2); alo[2] = f2tf32(xv2 - __uint_as_float(ahi[2]));
            ahi[3] = f2tf32(xv3); alo[3] = f2tf32(xv3 - __uint_as_float(ahi[3]));
            const int rr0 = pos0 + r4;
            const int rr1 = rr0 + 8;
            const bool zr = (t0 == 0) && (rr0 == 0);
#pragma unroll
            for (int nt = 0; nt < 8; nt++) {
                const uint32_t bh0 = wth[c4 * 72 + nt * 8 + r4];
                const uint32_t bh1 = wth[(c4 + 4) * 72 + nt * 8 + r4];
                const uint32_t bl0 = wtl[c4 * 72 + nt * 8 + r4];
                const uint32_t bl1 = wtl[(c4 + 4) * 72 + nt * 8 + r4];
                float dd[4] = {0.f, 0.f, 0.f, 0.f};
                mma1688tf32(dd, ahi, bh0, bh1);
                mma1688tf32(dd, alo, bh0, bh1);
                mma1688tf32(dd, ahi, bl0, bl1);
                const int c0 = nt * 8 + 2 * c4;
                const float ba0 = bas[c0], ba1 = bas[c0 + 1];
                float h00 = fmaxf(dd[0] + ba0, 0.f);
                float h01 = fmaxf(dd[1] + ba1, 0.f);
                const float h10 = fmaxf(dd[2] + ba0, 0.f);
                const float h11 = fmaxf(dd[3] + ba1, 0.f);
                if (zr) { h00 = 0.f; h01 = 0.f; }
                *(__half2*)(smem + HT_OFF + rr0 * 128 +
                            ((nt ^ ((rr0 >> 1) & 7)) * 16) + c4 * 4) =
                    __floats2half2_rn(h00, h01);
                *(__half2*)(smem + HT_OFF + rr1 * 128 +
                            ((nt ^ ((rr1 >> 1) & 7)) * 16) + c4 * 4) =
                    __floats2half2_rn(h10, h11);
            }
        }
        // position 128 (needed by k=2 at t=63): scalar
        if (tid < CH) {
            const int ch = tid;
            float s = bas[ch];
            const float* wr = wap + e * CH * ksz + ch * ksz;
            const int idx0 = 259 - pad;
            for (int k = 0; k < ksz; k++) s += wr[k] * xs[idx0 + k];
            s = fmaxf(s, 0.f);
            *(__half*)(smem + HT_OFF + 128 * 128 + (ch >> 3) * 16 + (ch & 7) * 2) =
                __float2half_rn(s);
        }
        __syncthreads();

        // conv2 GEMM: 3 k-shifts x 4 ci-steps, fp16 HMMA
        float acc[16];
#pragma unroll
        for (int i = 0; i < 16; i++) acc[i] = 0.f;

#pragma unroll
        for (int k = 0; k < 3; k++) {
            const int r = 2 * trow + k;
            const uint32_t abase = sb + HT_OFF + (uint32_t)r * 128;
            const uint32_t m = (uint32_t)(r >> 1) & 7u;
#pragma unroll
            for (int ks2 = 0; ks2 < 4; ks2++) {
                const uint32_t aaddr = abase + ((((uint32_t)ks2 * 2 + hb) ^ m) * 16);
                const uint32_t kb = (uint32_t)((k * 4 + ks2) * 32);
                uint32_t a[4], b0[4], b1[4];
                ldsm_x4(a[0], a[1], a[2], a[3], aaddr);
                ldsm_x4(b0[0], b0[1], b0[2], b0[3], sb + B_OFF + boff0 + kb);
                ldsm_x4(b1[0], b1[1], b1[2], b1[3], sb + B_OFF + boff1 + kb);
                mma16816(&acc[0],  a, b0[0], b0[1]);
                mma16816(&acc[4],  a, b0[2], b0[3]);
                mma16816(&acc[8],  a, b1[0], b1[1]);
                mma16816(&acc[12], a, b1[2], b1[3]);
            }
        }

        // epilogue: bias + relu + gate-weighted accumulate
        const float* bbe = bbp + e * CH;
#pragma unroll
        for (int nt = 0; nt < 4; nt++) {
            const int c0 = ch0 + nt * 8 + (lane & 3) * 2;
            const float b0 = bbe[c0], b1 = bbe[c0 + 1];
            facc[nt * 4 + 0] += wgt * fmaxf(acc[nt * 4 + 0] + b0, 0.f);
            facc[nt * 4 + 1] += wgt * fmaxf(acc[nt * 4 + 1] + b1, 0.f);
            facc[nt * 4 + 2] += wgt * fmaxf(acc[nt * 4 + 2] + b0, 0.f);
            facc[nt * 4 + 3] += wgt * fmaxf(acc[nt * 4 + 3] + b1, 0.f);
        }
    }

    // transpose via smem (reuse hT/B region) then coalesced stores
    __syncthreads();
    float* stage = (float*)(smem + HT_OFF) + wid * (32 * 17);
    {
        const int rt = lane >> 2;
#pragma unroll
        for (int nt = 0; nt < 4; nt++) {
            const int cl = nt * 8 + (lane & 3) * 2;
            stage[(cl    ) * 17 + rt]     = facc[nt * 4 + 0];
            stage[(cl + 1) * 17 + rt]     = facc[nt * 4 + 1];
            stage[(cl    ) * 17 + rt + 8] = facc[nt * 4 + 2];
            stage[(cl + 1) * 17 + rt + 8] = facc[nt * 4 + 3];
        }
    }
    __syncwarp();
    {
        const int tl = lane & 15;
        const size_t obase = (size_t)(b * 192 + br * 64 + ch0) * L2LEN +
                             t0 + tg * 16 + tl;
#pragma unroll
        for (int it = 0; it < 16; it++) {
            const int cl = it * 2 + (lane >> 4);
            out[obase + (size_t)cl * L2LEN] = stage[cl * 17 + tl];
        }
    }
}

// ---------------------------------------------------------------------------
extern "C" void kernel_launch(void* const* d_in, const int* in_sizes, int n_in,
                              void* d_out, int out_size) {
    const float* x   = (const float*)d_in[0];
    const float* Wg1 = (const float*)d_in[1];
    const float* bg1 = (const float*)d_in[2];
    const float* Wg2 = (const float*)d_in[3];
    const float* bg2 = (const float*)d_in[4];
    const float* Wg3 = (const float*)d_in[5];
    const float* bg3 = (const float*)d_in[6];
    const float* wa3 = (const float*)d_in[7];
    const float* ba3 = (const float*)d_in[8];
    const float* wb3 = (const float*)d_in[9];
    const float* bb3 = (const float*)d_in[10];
    const float* wa5 = (const float*)d_in[11];
    const float* ba5 = (const float*)d_in[12];
    const float* wb5 = (const float*)d_in[13];
    const float* bb5 = (const float*)d_in[14];
    const float* wa7 = (const float*)d_in[15];
    const float* ba7 = (const float*)d_in[16];
    const float* wb7 = (const float*)d_in[17];
    const float* bb7 = (const float*)d_in[18];
    float* out = (float*)d_out;

    k_prep<<<dim3(3, NE), 256>>>(wb3, wb5, wb7);
    k_stft<<<dim3(NFRAMES, NB), 128>>>(x);
    k_gate<<<NB, 256>>>(Wg1, bg1, Wg2, bg2, Wg3, bg3);

    (void)cudaFuncSetAttribute(k_expert,
                               cudaFuncAttributeMaxDynamicSharedMemorySize,
                               SMEM_BYTES);
    k_expert<<<dim3(NTILES, 3, NB), 256, SMEM_BYTES>>>(
        out, x,
        wa3, ba3, bb3,
        wa5, ba5, bb5,
        wa7, ba7, bb7);
}

// round 16
// speedup vs baseline: 5.3231x; 1.1026x over previous
#include <cuda_runtime.h>
#include <cuda_fp16.h>
#include <math.h>
#include <stdint.h>

#define NSAMP 4096
#define NFFT 256
#define HOP 64
#define NFRAMES 65
#define NBINS 129
#define NB 64
#define NE 8
#define CH 64
#define L2LEN 1024
#define TOUT 64
#define NTILES (L2LEN / TOUT)

#define BSTR 200      // B fp16 row stride (400 B -> conflict-free LDSM)

// smem byte offsets (k_expert)
#define HT_OFF   0                     // hT: 129 rows x 128 B (swizzled)
#define B_OFF    16512                 // 64 x 200 fp16 = 25600
#define W2_OFF   42112                 // conv1 weights, lane-linear: 512 tf32
#define XS_OFF   44160                 // 272 floats = 1088
#define BAS_OFF  45248                 // 64 floats
#define SMEM_BYTES 45504               // -> 4 CTAs/SM

// scratch
__device__ float g_mag[NB * NFRAMES * NBINS];
__device__ int   g_eidx[NB * 2];
__device__ float g_ew[NB * 2];
__device__ __align__(16) __half g_wb16[3 * NE * CH * BSTR];

__device__ __forceinline__ uint32_t smem_u32(const void* p) {
    uint32_t a;
    asm("{ .reg .u64 t; cvta.to.shared.u64 t, %1; cvt.u32.u64 %0, t; }"
        : "=r"(a) : "l"(p));
    return a;
}
__device__ __forceinline__ void ldsm_x4(uint32_t& r0, uint32_t& r1,
                                        uint32_t& r2, uint32_t& r3,
                                        uint32_t addr) {
    asm volatile("ldmatrix.sync.aligned.m8n8.x4.shared.b16 {%0,%1,%2,%3}, [%4];"
                 : "=r"(r0), "=r"(r1), "=r"(r2), "=r"(r3) : "r"(addr));
}
__device__ __forceinline__ void mma16816(float* d, const uint32_t* a,
                                         uint32_t b0, uint32_t b1) {
    asm volatile(
        "mma.sync.aligned.m16n8k16.row.col.f32.f16.f16.f32 "
        "{%0,%1,%2,%3}, {%4,%5,%6,%7}, {%8,%9}, {%0,%1,%2,%3};"
        : "+f"(d[0]), "+f"(d[1]), "+f"(d[2]), "+f"(d[3])
        : "r"(a[0]), "r"(a[1]), "r"(a[2]), "r"(a[3]), "r"(b0), "r"(b1));
}
__device__ __forceinline__ void mma1688tf32(float* d, const uint32_t* a,
                                            uint32_t b0, uint32_t b1) {
    asm volatile(
        "mma.sync.aligned.m16n8k8.row.col.f32.tf32.tf32.f32 "
        "{%0,%1,%2,%3}, {%4,%5,%6,%7}, {%8,%9}, {%0,%1,%2,%3};"
        : "+f"(d[0]), "+f"(d[1]), "+f"(d[2]), "+f"(d[3])
        : "r"(a[0]), "r"(a[1]), "r"(a[2]), "r"(a[3]), "r"(b0), "r"(b1));
}
__device__ __forceinline__ uint32_t f2tf32(float v) {
    uint32_t u;
    asm("cvt.rna.tf32.f32 %0, %1;" : "=r"(u) : "f"(v));
    return u;
}
#define CP_ASYNC16(dst, src) \
    asm volatile("cp.async.cg.shared.global [%0], [%1], 16;" \
                 :: "r"(dst), "l"(src) : "memory")
#define CP_ASYNC_COMMIT() asm volatile("cp.async.commit_group;" ::: "memory")
#define CP_ASYNC_WAIT0()  asm volatile("cp.async.wait_group 0;" ::: "memory")

// ---------------------------------------------------------------------------
// Kernel 0: conv2 weights -> fp16 LDSM-ready tiles, kk' = k*64 + ci
// ---------------------------------------------------------------------------
__global__ void __launch_bounds__(256) k_prep(
    const float* __restrict__ wb3, const float* __restrict__ wb5,
    const float* __restrict__ wb7) {
    const int br = blockIdx.x, e = blockIdx.y;
    const float* wb = ((br == 0) ? wb3 : (br == 1) ? wb5 : wb7) + e * CH * 192;
    __half* dst = g_wb16 + (br * NE + e) * (CH * BSTR);
    for (int idx = threadIdx.x; idx < CH * BSTR; idx += 256) {
        const int c = idx / BSTR;
        const int kk = idx - c * BSTR;
        float v = 0.f;
        if (kk < 192) v = wb[c * 192 + (kk & 63) * 3 + (kk >> 6)];
        dst[idx] = __float2half_rn(v);
    }
}

// ---------------------------------------------------------------------------
// Kernel 1: STFT magnitudes, symmetry-folded phasor DFT
// ---------------------------------------------------------------------------
__global__ void __launch_bounds__(128) k_stft(const float* __restrict__ x) {
    __shared__ float f[NFFT];
    __shared__ float fe[129], fo[129];
    const int fr = blockIdx.x, b = blockIdx.y, t = threadIdx.x;
    for (int i = t; i < NFFT; i += 128) {
        int m = fr * HOP + i - 128;
        if (m < 0) m = -m;
        else if (m >= NSAMP) m = 2 * NSAMP - 2 - m;
        const float win = 0.5f - 0.5f * cospif((float)i / 128.0f);
        f[i] = x[b * NSAMP + m] * win;
    }
    __syncthreads();
    if (t == 0) { fe[128] = 0.f; fo[128] = 0.f; }
    else        { fe[t] = f[t] + f[256 - t]; fo[t] = f[t] - f[256 - t]; }
    __syncthreads();

    float* magp = &g_mag[(b * NFRAMES + fr) * NBINS];
    if (t == 0) {
        float s0 = 0.f, s1 = 0.f;
#pragma unroll 8
        for (int n = 0; n < NFFT; n += 2) { s0 += f[n]; s1 += f[n + 1]; }
        magp[0] = fabsf(s0 + s1);
        magp[128] = fabsf(s0 - s1);
    } else {
        const float ang = (float)t / 128.0f;
        float c[4], s[4];
#pragma unroll
        for (int i = 0; i < 4; i++) {
            c[i] = cospif(ang * (float)(1 + i));
            s[i] = sinpif(ang * (float)(1 + i));
        }
        const float cD = cospif(ang * 4.0f), sD = sinpif(ang * 4.0f);
        float re = f[0] + ((t & 1) ? -f[128] : f[128]);
        float im = 0.f;
#pragma unroll 4
        for (int j = 0; j < 32; j++) {
            const int nb = 4 * j + 1;
#pragma unroll
            for (int i = 0; i < 4; i++) {
                re += fe[nb + i] * c[i];
                im += fo[nb + i] * s[i];
                const float cn = c[i] * cD - s[i] * sD;
                s[i] = c[i] * sD + s[i] * cD; c[i] = cn;
            }
        }
        magp[t] = sqrtf(re * re + im * im);
    }
}

// ---------------------------------------------------------------------------
// Kernel 2: pooling + gating MLP + top-2 + softmax
// ---------------------------------------------------------------------------
__global__ void __launch_bounds__(256) k_gate(
    const float* __restrict__ Wg1, const float* __restrict__ bg1,
    const float* __restrict__ Wg2, const float* __restrict__ bg2,
    const float* __restrict__ Wg3, const float* __restrict__ bg3) {
    __shared__ float p[NBINS]; __shared__ float h1[256];
    __shared__ float h2[128];  __shared__ float lg[NE];
    const int b = blockIdx.x, t = threadIdx.x;
    if (t < NBINS) {
        float s = 0.f;
        for (int fr = 0; fr < NFRAMES; fr++) s += g_mag[(b * NFRAMES + fr) * NBINS + t];
        p[t] = s * (1.0f / NFRAMES);
    }
    __syncthreads();
    { float s = bg1[t];
      for (int i = 0; i < NBINS; i++) s += p[i] * Wg1[i * 256 + t];
      h1[t] = fmaxf(s, 0.f); }
    __syncthreads();
    if (t < 128) {
        float s = bg2[t];
        for (int i = 0; i < 256; i++) s += h1[i] * Wg2[i * 128 + t];
        h2[t] = fmaxf(s, 0.f);
    }
    __syncthreads();
    if (t < NE) {
        float s = bg3[t];
        for (int i = 0; i < 128; i++) s += h2[i] * Wg3[i * NE + t];
        lg[t] = s;
    }
    __syncthreads();
    if (t == 0) {
        int i0 = 0; float v0 = lg[0];
        for (int j = 1; j < NE; j++) if (lg[j] > v0) { v0 = lg[j]; i0 = j; }
        int i1 = (i0 == 0) ? 1 : 0; float v1 = lg[i1];
        for (int j = 0; j < NE; j++) if (j != i0 && lg[j] > v1) { v1 = lg[j]; i1 = j; }
        const float e = expf(v1 - v0);
        const float inv = 1.f / (1.f + e);
        g_eidx[b * 2] = i0; g_eidx[b * 2 + 1] = i1;
        g_ew[b * 2] = inv;  g_ew[b * 2 + 1] = e * inv;
    }
}

// ---------------------------------------------------------------------------
// Kernel 3: fused top-2 expert stack. conv1 via tf32 MMA (x split hi/lo,
// weights single tf32, 2 passes), conv2 via fp16 HMMA from swizzled hT.
// B staged with cp.async, wait deferred past conv1.
// grid (16, 3, NB), 256 threads, 45.5KB smem -> 4 CTAs/SM.
// ---------------------------------------------------------------------------
__global__ void __launch_bounds__(256, 4) k_expert(
    float* __restrict__ out, const float* __restrict__ x,
    const float* __restrict__ wa3, const float* __restrict__ ba3,
    const float* __restrict__ bb3,
    const float* __restrict__ wa5, const float* __restrict__ ba5,
    const float* __restrict__ bb5,
    const float* __restrict__ wa7, const float* __restrict__ ba7,
    const float* __restrict__ bb7) {
    extern __shared__ char smem[];
    const uint32_t sb = smem_u32(smem);
    float* xs  = (float*)(smem + XS_OFF);
    float* bas = (float*)(smem + BAS_OFF);

    const int tid  = threadIdx.x;
    const int wid  = tid >> 5;
    const int lane = tid & 31;
    const int tile = blockIdx.x, br = blockIdx.y, b = blockIdx.z;
    const int t0   = tile * TOUT;
    const int tg   = wid >> 1;
    const int ch0  = (wid & 1) * 32;
    const int ksz  = 3 + 2 * br;
    const int pad  = ksz >> 1;

    const float* wap = (br == 0) ? wa3 : ((br == 1) ? wa5 : wa7);
    const float* bap = (br == 0) ? ba3 : ((br == 1) ? ba5 : ba7);
    const float* bbp = (br == 0) ? bb3 : ((br == 1) ? bb5 : bb7);

    const int   eidx[2] = { g_eidx[b * 2], g_eidx[b * 2 + 1] };
    const float ewgt[2] = { g_ew[b * 2],   g_ew[b * 2 + 1] };

    // stage x window: xi in [4*t0-5, 4*t0+266]
    const int xlo = 4 * t0 - 5;
    for (int i = tid; i < 272; i += 256) {
        const int xi = xlo + i;
        xs[i] = (xi >= 0 && xi < NSAMP) ? x[b * NSAMP + xi] : 0.f;
    }

    // conv1 MMA fragment lane constants
    const int r4 = lane >> 2, c4 = lane & 3;
    // conv2 ldmatrix lane constants
    const int trow = tg * 16 + (lane & 15);
    const uint32_t hb = (lane & 16) ? 1u : 0u;
    const int brow = (lane & 7) + ((lane >> 1) & 8);
    const int bko  = (lane & 8) ? 8 : 0;
    const uint32_t boff0 = (uint32_t)(((ch0 + brow) * BSTR + bko) * 2);
    const uint32_t boff1 = (uint32_t)(((ch0 + 16 + brow) * BSTR + bko) * 2);

    float facc[16];
#pragma unroll
    for (int i = 0; i < 16; i++) facc[i] = 0.f;

    for (int ei = 0; ei < 2; ei++) {
        const int e = eidx[ei];
        const float wgt = ewgt[ei];
        __syncthreads();   // tiles free (prev GEMM done); xs ready (ei=0)

        // B fp16 tile via cp.async (wait deferred past conv1)
        {
            const char* src = (const char*)(g_wb16 + (br * NE + e) * (CH * BSTR));
            for (int i = tid; i < (CH * BSTR * 2) / 16; i += 256)
                CP_ASYNC16(sb + B_OFF + i * 16, src + i * 16);
            CP_ASYNC_COMMIT();
        }
        // conv1 weights, lane-linear layout W2[nt][k][ch8] + bias
        {
            uint32_t* w2 = (uint32_t*)(smem + W2_OFF);
            for (int idx = tid; idx < 512; idx += 256) {
                const int nt = idx >> 6, k = (idx >> 3) & 7, rch = idx & 7;
                const float v = (k < ksz)
                    ? wap[e * CH * ksz + (nt * 8 + rch) * ksz + k] : 0.f;
                w2[idx] = f2tf32(v);
            }
            if (tid < CH) bas[tid] = bap[e * CH + tid];
        }
        __syncthreads();

        // conv1 via tf32 MMA: D[pos16, ch64] per warp; A frags direct from xs
        {
            const uint32_t* w2 = (const uint32_t*)(smem + W2_OFF);
            const int pos0 = wid * 16;
            const int base0 = 2 * (pos0 + r4) + 3 - pad;
            const float xv0 = xs[base0 + c4];
            const float xv1 = xs[base0 + 16 + c4];
            const float xv2 = xs[base0 + c4 + 4];
            const float xv3 = xs[base0 + 16 + c4 + 4];
            uint32_t ahi[4], alo[4];
            ahi[0] = f2tf32(xv0); alo[0] = f2tf32(xv0 - __uint_as_float(ahi[0]));
            ahi[1] = f2tf32(xv1); alo[1] = f2tf32(xv1 - __uint_as_float(ahi[1]));
            ahi[2] = f2tf32(xv2); alo[2] = f2tf32(xv2 - __uint_as_float(ahi[2]));
            ahi[3] = f2tf32(xv3); alo[3] = f2tf32(xv3 - __uint_as_float(ahi[3]));
            const int rr0 = pos0 + r4;
            const int rr1 = rr0 + 8;
            const bool zr = (t0 == 0) && (rr0 == 0);
#pragma unroll
            for (int nt = 0; nt < 8; nt++) {
                const uint32_t bh0 = w2[nt * 64 + c4 * 8 + r4];
                const uint32_t bh1 = w2[nt * 64 + (c4 + 4) * 8 + r4];
                float dd[4] = {0.f, 0.f, 0.f, 0.f};
                mma1688tf32(dd, ahi, bh0, bh1);
                mma1688tf32(dd, alo, bh0, bh1);
                const int c0 = nt * 8 + 2 * c4;
                const float ba0 = bas[c0], ba1 = bas[c0 + 1];
                float h00 = fmaxf(dd[0] + ba0, 0.f);
                float h01 = fmaxf(dd[1] + ba1, 0.f);
                const float h10 = fmaxf(dd[2] + ba0, 0.f);
                const float h11 = fmaxf(dd[3] + ba1, 0.f);
                if (zr) { h00 = 0.f; h01 = 0.f; }
                *(__half2*)(smem + HT_OFF + rr0 * 128 +
                            ((nt ^ ((rr0 >> 1) & 7)) * 16) + c4 * 4) =
                    __floats2half2_rn(h00, h01);
                *(__half2*)(smem + HT_OFF + rr1 * 128 +
                            ((nt ^ ((rr1 >> 1) & 7)) * 16) + c4 * 4) =
                    __floats2half2_rn(h10, h11);
            }
        }
        // position 128 (needed by k=2 at t=63): scalar
        if (tid < CH) {
            const int ch = tid;
            float s = bas[ch];
            const float* wr = wap + e * CH * ksz + ch * ksz;
            const int idx0 = 259 - pad;
            for (int k = 0; k < ksz; k++) s += wr[k] * xs[idx0 + k];
            s = fmaxf(s, 0.f);
            *(__half*)(smem + HT_OFF + 128 * 128 + (ch >> 3) * 16 + (ch & 7) * 2) =
                __float2half_rn(s);
        }
        CP_ASYNC_WAIT0();
        __syncthreads();

        // conv2 GEMM: 3 k-shifts x 4 ci-steps, fp16 HMMA
        float acc[16];
#pragma unroll
        for (int i = 0; i < 16; i++) acc[i] = 0.f;

#pragma unroll
        for (int k = 0; k < 3; k++) {
            const int r = 2 * trow + k;
            const uint32_t abase = sb + HT_OFF + (uint32_t)r * 128;
            const uint32_t m = (uint32_t)(r >> 1) & 7u;
#pragma unroll
            for (int ks2 = 0; ks2 < 4; ks2++) {
                const uint32_t aaddr = abase + ((((uint32_t)ks2 * 2 + hb) ^ m) * 16);
                const uint32_t kb = (uint32_t)((k * 4 + ks2) * 32);
                uint32_t a[4], b0[4], b1[4];
                ldsm_x4(a[0], a[1], a[2], a[3], aaddr);
                ldsm_x4(b0[0], b0[1], b0[2], b0[3], sb + B_OFF + boff0 + kb);
                ldsm_x4(b1[0], b1[1], b1[2], b1[3], sb + B_OFF + boff1 + kb);
                mma16816(&acc[0],  a, b0[0], b0[1]);
                mma16816(&acc[4],  a, b0[2], b0[3]);
                mma16816(&acc[8],  a, b1[0], b1[1]);
                mma16816(&acc[12], a, b1[2], b1[3]);
            }
        }

        // epilogue: bias + relu + gate-weighted accumulate
        const float* bbe = bbp + e * CH;
#pragma unroll
        for (int nt = 0; nt < 4; nt++) {
            const int c0 = ch0 + nt * 8 + (lane & 3) * 2;
            const float b0 = bbe[c0], b1 = bbe[c0 + 1];
            facc[nt * 4 + 0] += wgt * fmaxf(acc[nt * 4 + 0] + b0, 0.f);
            facc[nt * 4 + 1] += wgt * fmaxf(acc[nt * 4 + 1] + b1, 0.f);
            facc[nt * 4 + 2] += wgt * fmaxf(acc[nt * 4 + 2] + b0, 0.f);
            facc[nt * 4 + 3] += wgt * fmaxf(acc[nt * 4 + 3] + b1, 0.f);
        }
    }

    // transpose via smem (reuse hT/B region) then coalesced stores
    __syncthreads();
    float* stage = (float*)(smem + HT_OFF) + wid * (32 * 17);
    {
        const int rt = lane >> 2;
#pragma unroll
        for (int nt = 0; nt < 4; nt++) {
            const int cl = nt * 8 + (lane & 3) * 2;
            stage[(cl    ) * 17 + rt]     = facc[nt * 4 + 0];
            stage[(cl + 1) * 17 + rt]     = facc[nt * 4 + 1];
            stage[(cl    ) * 17 + rt + 8] = facc[nt * 4 + 2];
            stage[(cl + 1) * 17 + rt + 8] = facc[nt * 4 + 3];
        }
    }
    __syncwarp();
    {
        const int tl = lane & 15;
        const size_t obase = (size_t)(b * 192 + br * 64 + ch0) * L2LEN +
                             t0 + tg * 16 + tl;
#pragma unroll
        for (int it = 0; it < 16; it++) {
            const int cl = it * 2 + (lane >> 4);
            out[obase + (size_t)cl * L2LEN] = stage[cl * 17 + tl];
        }
    }
}

// ---------------------------------------------------------------------------
extern "C" void kernel_launch(void* const* d_in, const int* in_sizes, int n_in,
                              void* d_out, int out_size) {
    const float* x   = (const float*)d_in[0];
    const float* Wg1 = (const float*)d_in[1];
    const float* bg1 = (const float*)d_in[2];
    const float* Wg2 = (const float*)d_in[3];
    const float* bg2 = (const float*)d_in[4];
    const float* Wg3 = (const float*)d_in[5];
    const float* bg3 = (const float*)d_in[6];
    const float* wa3 = (const float*)d_in[7];
    const float* ba3 = (const float*)d_in[8];
    const float* wb3 = (const float*)d_in[9];
    const float* bb3 = (const float*)d_in[10];
    const float* wa5 = (const float*)d_in[11];
    const float* ba5 = (const float*)d_in[12];
    const float* wb5 = (const float*)d_in[13];
    const float* bb5 = (const float*)d_in[14];
    const float* wa7 = (const float*)d_in[15];
    const float* ba7 = (const float*)d_in[16];
    const float* wb7 = (const float*)d_in[17];
    const float* bb7 = (const float*)d_in[18];
    float* out = (float*)d_out;

    k_prep<<<dim3(3, NE), 256>>>(wb3, wb5, wb7);
    k_stft<<<dim3(NFRAMES, NB), 128>>>(x);
    k_gate<<<NB, 256>>>(Wg1, bg1, Wg2, bg2, Wg3, bg3);

    (void)cudaFuncSetAttribute(k_expert,
                               cudaFuncAttributeMaxDynamicSharedMemorySize,
                               SMEM_BYTES);
    k_expert<<<dim3(NTILES, 3, NB), 256, SMEM_BYTES>>>(
        out, x,
        wa3, ba3, bb3,
        wa5, ba5, bb5,
        wa7, ba7, bb7);
}